// round 1
// baseline (speedup 1.0000x reference)
#include <cuda_runtime.h>
#include <math.h>

// Problem dims
#define NTOK 8192      // B*S
#define DDIM 1024      // d_model
#define HDIM 2048      // H
#define MDIM 64        // M (moe hidden)
#define EEXP 8         // experts
#define HHALF 1024     // H/2

// Scratch: spk_enc(8192*2048) cont(8192*64) gates(8192*8) hbuf(8192*1024)
//          outflat(8192*64) spk_moe(8192*2048) decoded(8192*1024)
#define SCRATCH_FLOATS (16777216UL + 524288UL + 65536UL + 8388608UL + 524288UL + 16777216UL + 8388608UL)
__device__ float g_scratch[SCRATCH_FLOATS];

// ---------------------------------------------------------------------------
// Generic tiled fp32 GEMM: C = epilogue(A[NxK] @ W[KxHout] + bias)
// ACT: 0=none, 1=sigmoid, 2=relu.  RS: multiply row by rowscale[row*rs_stride]
// ACCUM: C += v instead of C = v
// All dims are multiples of tile sizes for every launch below (no bounds checks).
// ---------------------------------------------------------------------------
template<int BM, int BN, int BK, int TM, int TN, int ACT, bool ACCUM, bool RS>
__global__ __launch_bounds__((BM / TM) * (BN / TN))
void gemm_kernel(const float* __restrict__ A, const float* __restrict__ W,
                 const float* __restrict__ bias, float* __restrict__ C,
                 int N, int K, int Hout,
                 const float* __restrict__ rowscale, int rs_stride)
{
    constexpr int THREADS = (BM / TM) * (BN / TN);
    __shared__ float As[BK][BM];
    __shared__ float Bs[BK][BN];

    const int tid  = threadIdx.x;
    const int bm0  = blockIdx.y * BM;
    const int bn0  = blockIdx.x * BN;
    const int tcol = tid % (BN / TN);
    const int trow = tid / (BN / TN);

    float acc[TM][TN];
#pragma unroll
    for (int i = 0; i < TM; i++)
#pragma unroll
        for (int j = 0; j < TN; j++) acc[i][j] = 0.0f;

    constexpr int A_LD_ITERS = (BM * BK) / (THREADS * 4);
    constexpr int B_LD_ITERS = (BK * BN) / (THREADS * 4);

    for (int k0 = 0; k0 < K; k0 += BK) {
        // Load A tile (BM x BK) as float4 along K, store transposed
#pragma unroll
        for (int it = 0; it < A_LD_ITERS; it++) {
            int idx = tid + it * THREADS;            // float4 index in tile
            int r   = idx / (BK / 4);
            int c4  = idx % (BK / 4);
            float4 v = *(const float4*)&A[(size_t)(bm0 + r) * K + k0 + c4 * 4];
            As[c4 * 4 + 0][r] = v.x;
            As[c4 * 4 + 1][r] = v.y;
            As[c4 * 4 + 2][r] = v.z;
            As[c4 * 4 + 3][r] = v.w;
        }
        // Load B tile (BK x BN), row-major, float4 along Hout
#pragma unroll
        for (int it = 0; it < B_LD_ITERS; it++) {
            int idx = tid + it * THREADS;
            int r   = idx / (BN / 4);
            int c4  = idx % (BN / 4);
            *(float4*)&Bs[r][c4 * 4] =
                *(const float4*)&W[(size_t)(k0 + r) * Hout + bn0 + c4 * 4];
        }
        __syncthreads();

#pragma unroll
        for (int k = 0; k < BK; k++) {
            float a[TM], b[TN];
#pragma unroll
            for (int i = 0; i < TM; i++) a[i] = As[k][trow * TM + i];
#pragma unroll
            for (int j = 0; j < TN; j++) b[j] = Bs[k][tcol * TN + j];
#pragma unroll
            for (int i = 0; i < TM; i++)
#pragma unroll
                for (int j = 0; j < TN; j++)
                    acc[i][j] = fmaf(a[i], b[j], acc[i][j]);
        }
        __syncthreads();
    }

    // Epilogue
    float rs[TM];
    if (RS) {
#pragma unroll
        for (int i = 0; i < TM; i++)
            rs[i] = rowscale[(size_t)(bm0 + trow * TM + i) * rs_stride];
    }
#pragma unroll
    for (int i = 0; i < TM; i++) {
        const int row = bm0 + trow * TM + i;
#pragma unroll
        for (int j = 0; j < TN; j++) {
            const int col = bn0 + tcol * TN + j;
            float v = acc[i][j] + bias[col];
            if (ACT == 1) v = 1.0f / (1.0f + expf(-v));
            if (ACT == 2) v = fmaxf(v, 0.0f);
            if (RS) v *= rs[i];
            size_t off = (size_t)row * Hout + col;
            if (ACCUM) C[off] += v; else C[off] = v;
        }
    }
}

// ---------------------------------------------------------------------------
// Router: hid = tanh(cont @ rW1 + rb1); logits = hid @ rW2 + rb2;
// softmax -> top-2 -> renormalize -> dense gates (N, 8)
// One block (64 threads) per token.
// ---------------------------------------------------------------------------
__global__ void router_kernel(const float* __restrict__ cont,
                              const float* __restrict__ rW1, const float* __restrict__ rb1,
                              const float* __restrict__ rW2, const float* __restrict__ rb2,
                              float* __restrict__ gates)
{
    __shared__ float cs[64];
    __shared__ float hid[64];
    __shared__ float logit[8];
    const int n = blockIdx.x;
    const int t = threadIdx.x;

    cs[t] = cont[(size_t)n * MDIM + t];
    __syncthreads();

    float a = rb1[t];
#pragma unroll
    for (int m = 0; m < 64; m++) a = fmaf(cs[m], rW1[m * 64 + t], a);
    hid[t] = tanhf(a);
    __syncthreads();

    if (t < EEXP) {
        float l = rb2[t];
#pragma unroll
        for (int j = 0; j < 64; j++) l = fmaf(hid[j], rW2[j * EEXP + t], l);
        logit[t] = l;
    }
    __syncthreads();

    if (t == 0) {
        float mx = logit[0];
        for (int e = 1; e < EEXP; e++) mx = fmaxf(mx, logit[e]);
        float p[EEXP];
        for (int e = 0; e < EEXP; e++) p[e] = expf(logit[e] - mx);
        // top-2 (earliest index on ties, matching lax.top_k)
        int i1 = 0;
        for (int e = 1; e < EEXP; e++) if (p[e] > p[i1]) i1 = e;
        int i2 = (i1 == 0) ? 1 : 0;
        for (int e = 0; e < EEXP; e++) if (e != i1 && p[e] > p[i2]) i2 = e;
        float denom = p[i1] + p[i2];   // softmax normalizer cancels in renorm
        float g[EEXP];
        for (int e = 0; e < EEXP; e++) g[e] = 0.0f;
        g[i1] = p[i1] / denom;
        g[i2] = p[i2] / denom;
        for (int e = 0; e < EEXP; e++) gates[(size_t)n * EEXP + e] = g[e];
    }
}

// ---------------------------------------------------------------------------
// LayerNorm over D=1024, one block (256 threads) per row.
// ---------------------------------------------------------------------------
__global__ void layernorm_kernel(const float* __restrict__ x,
                                 const float* __restrict__ g, const float* __restrict__ b,
                                 float* __restrict__ out)
{
    const int n = blockIdx.x;
    const int t = threadIdx.x;
    const float* row = x + (size_t)n * DDIM;

    float v[4];
    float s = 0.0f, s2 = 0.0f;
#pragma unroll
    for (int i = 0; i < 4; i++) {
        v[i] = row[t + i * 256];
        s += v[i];
        s2 += v[i] * v[i];
    }
#pragma unroll
    for (int o = 16; o > 0; o >>= 1) {
        s  += __shfl_xor_sync(0xFFFFFFFFu, s, o);
        s2 += __shfl_xor_sync(0xFFFFFFFFu, s2, o);
    }
    __shared__ float sh1[8], sh2[8];
    __shared__ float mu_s, rstd_s;
    const int warp = t >> 5, lane = t & 31;
    if (lane == 0) { sh1[warp] = s; sh2[warp] = s2; }
    __syncthreads();
    if (t == 0) {
        float S = 0.0f, S2 = 0.0f;
        for (int w = 0; w < 8; w++) { S += sh1[w]; S2 += sh2[w]; }
        float mu  = S / (float)DDIM;
        float var = S2 / (float)DDIM - mu * mu;
        mu_s   = mu;
        rstd_s = rsqrtf(var + 1e-5f);
    }
    __syncthreads();
    const float mu = mu_s, rstd = rstd_s;
    float* orow = out + (size_t)n * DDIM;
#pragma unroll
    for (int i = 0; i < 4; i++) {
        int col = t + i * 256;
        orow[col] = (v[i] - mu) * rstd * g[col] + b[col];
    }
}

// ---------------------------------------------------------------------------
// kernel_launch: graph-capturable pipeline on the default stream
// ---------------------------------------------------------------------------
extern "C" void kernel_launch(void* const* d_in, const int* in_sizes, int n_in,
                              void* d_out, int out_size)
{
    const float* X     = (const float*)d_in[0];
    const float* enc_W = (const float*)d_in[1];
    const float* enc_b = (const float*)d_in[2];
    const float* s2c_W = (const float*)d_in[3];
    const float* s2c_b = (const float*)d_in[4];
    const float* rW1   = (const float*)d_in[5];
    const float* rb1   = (const float*)d_in[6];
    const float* rW2   = (const float*)d_in[7];
    const float* rb2   = (const float*)d_in[8];
    const float* We1   = (const float*)d_in[9];
    const float* be1   = (const float*)d_in[10];
    const float* We2   = (const float*)d_in[11];
    const float* be2   = (const float*)d_in[12];
    const float* c2s_W = (const float*)d_in[13];
    const float* c2s_b = (const float*)d_in[14];
    const float* dec_W = (const float*)d_in[15];
    const float* dec_b = (const float*)d_in[16];
    const float* ln_g  = (const float*)d_in[17];
    const float* ln_b  = (const float*)d_in[18];

    float* base = nullptr;
    cudaGetSymbolAddress((void**)&base, g_scratch);
    float* spk_enc = base;
    float* cont    = spk_enc + (size_t)NTOK * HDIM;
    float* gates   = cont    + (size_t)NTOK * MDIM;
    float* hbuf    = gates   + (size_t)NTOK * EEXP;
    float* outflat = hbuf    + (size_t)NTOK * HHALF;
    float* spk_moe = outflat + (size_t)NTOK * MDIM;
    float* decoded = spk_moe + (size_t)NTOK * HDIM;

    const dim3 blk(256);

    // 1) encoder: spikes_enc = sigmoid(X @ enc_W + enc_b)   (8192x1024 @ 1024x2048)
    gemm_kernel<128, 128, 16, 8, 8, 1, false, false>
        <<<dim3(HDIM / 128, NTOK / 128), blk>>>(X, enc_W, enc_b, spk_enc,
                                                NTOK, DDIM, HDIM, nullptr, 0);

    // 2) s2c: cont = spikes_enc @ s2c_W + s2c_b             (8192x2048 @ 2048x64)
    gemm_kernel<128, 64, 16, 8, 4, 0, false, false>
        <<<dim3(1, NTOK / 128), blk>>>(spk_enc, s2c_W, s2c_b, cont,
                                       NTOK, HDIM, MDIM, nullptr, 0);

    // 3) router -> dense gates (8192 x 8)
    router_kernel<<<NTOK, 64>>>(cont, rW1, rb1, rW2, rb2, gates);

    // 4) experts: outflat = sum_e gates[:,e] * (relu(cont@We1_e+be1_e) @ We2_e + be2_e)
    for (int e = 0; e < EEXP; e++) {
        gemm_kernel<128, 128, 16, 8, 8, 2, false, false>
            <<<dim3(HHALF / 128, NTOK / 128), blk>>>(
                cont, We1 + (size_t)e * MDIM * HHALF, be1 + (size_t)e * HHALF,
                hbuf, NTOK, MDIM, HHALF, nullptr, 0);
        if (e == 0) {
            gemm_kernel<128, 64, 16, 8, 4, 0, false, true>
                <<<dim3(1, NTOK / 128), blk>>>(
                    hbuf, We2 + (size_t)e * HHALF * MDIM, be2 + (size_t)e * MDIM,
                    outflat, NTOK, HHALF, MDIM, gates + e, EEXP);
        } else {
            gemm_kernel<128, 64, 16, 8, 4, 0, true, true>
                <<<dim3(1, NTOK / 128), blk>>>(
                    hbuf, We2 + (size_t)e * HHALF * MDIM, be2 + (size_t)e * MDIM,
                    outflat, NTOK, HHALF, MDIM, gates + e, EEXP);
        }
    }

    // 5) c2s: spikes_moe = sigmoid(outflat @ c2s_W + c2s_b) (8192x64 @ 64x2048)
    gemm_kernel<128, 128, 16, 8, 8, 1, false, false>
        <<<dim3(HDIM / 128, NTOK / 128), blk>>>(outflat, c2s_W, c2s_b, spk_moe,
                                                NTOK, MDIM, HDIM, nullptr, 0);

    // 6) decoder: decoded = sigmoid(spikes_moe @ dec_W + dec_b) (8192x2048 @ 2048x1024)
    gemm_kernel<128, 128, 16, 8, 8, 1, false, false>
        <<<dim3(DDIM / 128, NTOK / 128), blk>>>(spk_moe, dec_W, dec_b, decoded,
                                                NTOK, HDIM, DDIM, nullptr, 0);

    // 7) layernorm -> d_out
    layernorm_kernel<<<NTOK, 256>>>(decoded, ln_g, ln_b, (float*)d_out);
}

// round 2
// speedup vs baseline: 2.4385x; 2.4385x over previous
#include <cuda_runtime.h>
#include <math.h>

// Problem dims
#define NTOK 8192      // B*S
#define DDIM 1024      // d_model
#define HDIM 2048      // H
#define MDIM 64        // M (moe hidden)
#define EEXP 8         // experts
#define HHALF 1024     // H/2
#define HBIG  8192     // E * H/2

// ---------------------------------------------------------------------------
// Scratch (device globals; no allocations allowed)
// ---------------------------------------------------------------------------
__device__ float g_spk_enc[(size_t)NTOK * HDIM];
__device__ float g_cont[(size_t)NTOK * MDIM];
__device__ float g_gates[(size_t)NTOK * EEXP];
__device__ float g_hbig[(size_t)NTOK * HBIG];     // gate-scaled expert hidden, 256MB
__device__ float g_outflat[(size_t)NTOK * MDIM];
__device__ float g_spk_moe[(size_t)NTOK * HDIM];
__device__ float g_decoded[(size_t)NTOK * DDIM];

__device__ __forceinline__ unsigned f2tf(float x) {
    unsigned u;
    asm("cvt.rna.tf32.f32 %0, %1;" : "=r"(u) : "f"(x));
    return u;
}

// ---------------------------------------------------------------------------
// tf32 tensor-core GEMM:  C[N x Hout] = epi(A[N x K] @ W[K x Hout] + bias)
//   BK = 16 fixed. Warp tile = (MFRAG*16) x (NFRAG*8), mma.m16n8k8.
//   ACT: 0=none 1=sigmoid 2=relu
//   ESTRIDE: B is expert-blocked We1 (E,64,1024): col n -> expert n>>10
//   GCOL: scale output by gates[row*8 + (col>>10)]   (after activation)
//   BE2:  add sum_e gates[row,e]*be2[e*64+col] instead of bias
// ---------------------------------------------------------------------------
template<int BM, int BN, int WM, int WN, int MFRAG, int NFRAG,
         int ACT, bool ESTRIDE, bool GCOL, bool BE2>
__global__ __launch_bounds__(WM * WN * 32)
void mma_gemm(const float* __restrict__ A, const float* __restrict__ W,
              const float* __restrict__ bias, float* __restrict__ C,
              int K, int Hout,
              const float* __restrict__ gates, const float* __restrict__ be2)
{
    constexpr int THREADS = WM * WN * 32;
    constexpr int AS = 20;          // A smem row stride (16 + 4 pad) -> conflict free frag loads
    constexpr int BS = BN + 8;      // B smem row stride -> conflict free frag loads
    constexpr int WTM = MFRAG * 16;
    constexpr int WTN = NFRAG * 8;
    constexpr int ALD = (BM * 16) / (THREADS * 4);   // float4 loads per thread (A)
    constexpr int BLD = (16 * BN) / (THREADS * 4);   // float4 loads per thread (B)

    __shared__ unsigned As[2][BM * AS];
    __shared__ unsigned Bs[2][16 * BS];

    const int tid  = threadIdx.x;
    const int bm0  = blockIdx.y * BM;
    const int bn0  = blockIdx.x * BN;
    const int w    = tid >> 5;
    const int lane = tid & 31;
    const int g    = lane >> 2;
    const int tg   = lane & 3;
    const int wm   = w / WN;
    const int wn   = w % WN;

    float c[MFRAG][NFRAG][4];
#pragma unroll
    for (int i = 0; i < MFRAG; i++)
#pragma unroll
        for (int j = 0; j < NFRAG; j++)
#pragma unroll
            for (int q = 0; q < 4; q++) c[i][j][q] = 0.0f;

    float4 areg[ALD], breg[BLD];

    // ---- stage loaders ----
    auto loadG = [&](int k0) {
#pragma unroll
        for (int it = 0; it < ALD; it++) {
            int idx = tid + it * THREADS;     // float4 index
            int r   = idx >> 2;               // 4 float4 per 16-wide row
            int c4  = idx & 3;
            areg[it] = *(const float4*)&A[(size_t)(bm0 + r) * K + k0 + c4 * 4];
        }
#pragma unroll
        for (int it = 0; it < BLD; it++) {
            int idx = tid + it * THREADS;
            int r   = idx / (BN / 4);
            int c4  = idx % (BN / 4);
            size_t gaddr;
            if (ESTRIDE) {
                int n = bn0 + c4 * 4;
                int e = n >> 10;
                gaddr = (size_t)e * (MDIM * HHALF) + (size_t)(k0 + r) * HHALF + (n & 1023);
            } else {
                gaddr = (size_t)(k0 + r) * Hout + bn0 + c4 * 4;
            }
            breg[it] = *(const float4*)&W[gaddr];
        }
    };
    auto stage = [&](int buf) {
#pragma unroll
        for (int it = 0; it < ALD; it++) {
            int idx = tid + it * THREADS;
            int r   = idx >> 2;
            int c4  = idx & 3;
            uint4 v = make_uint4(f2tf(areg[it].x), f2tf(areg[it].y),
                                 f2tf(areg[it].z), f2tf(areg[it].w));
            *(uint4*)&As[buf][r * AS + c4 * 4] = v;
        }
#pragma unroll
        for (int it = 0; it < BLD; it++) {
            int idx = tid + it * THREADS;
            int r   = idx / (BN / 4);
            int c4  = idx % (BN / 4);
            uint4 v = make_uint4(f2tf(breg[it].x), f2tf(breg[it].y),
                                 f2tf(breg[it].z), f2tf(breg[it].w));
            *(uint4*)&Bs[buf][r * BS + c4 * 4] = v;
        }
    };
    auto compute = [&](int buf) {
#pragma unroll
        for (int ks = 0; ks < 2; ks++) {      // 16 / 8
            unsigned a[MFRAG][4], b[NFRAG][2];
#pragma unroll
            for (int mf = 0; mf < MFRAG; mf++) {
                int m0 = wm * WTM + mf * 16;
                const unsigned* ap = As[buf];
                a[mf][0] = ap[(m0 + g)     * AS + ks * 8 + tg];
                a[mf][1] = ap[(m0 + g + 8) * AS + ks * 8 + tg];
                a[mf][2] = ap[(m0 + g)     * AS + ks * 8 + tg + 4];
                a[mf][3] = ap[(m0 + g + 8) * AS + ks * 8 + tg + 4];
            }
#pragma unroll
            for (int nf = 0; nf < NFRAG; nf++) {
                int n0 = wn * WTN + nf * 8 + g;
                b[nf][0] = Bs[buf][(ks * 8 + tg)     * BS + n0];
                b[nf][1] = Bs[buf][(ks * 8 + tg + 4) * BS + n0];
            }
#pragma unroll
            for (int mf = 0; mf < MFRAG; mf++)
#pragma unroll
                for (int nf = 0; nf < NFRAG; nf++) {
                    asm volatile(
                        "mma.sync.aligned.m16n8k8.row.col.f32.tf32.tf32.f32 "
                        "{%0,%1,%2,%3}, {%4,%5,%6,%7}, {%8,%9}, {%0,%1,%2,%3};\n"
                        : "+f"(c[mf][nf][0]), "+f"(c[mf][nf][1]),
                          "+f"(c[mf][nf][2]), "+f"(c[mf][nf][3])
                        : "r"(a[mf][0]), "r"(a[mf][1]), "r"(a[mf][2]), "r"(a[mf][3]),
                          "r"(b[nf][0]), "r"(b[nf][1]));
                }
        }
    };

    // ---- main loop (double buffered) ----
    const int nk = K / 16;
    loadG(0);
    stage(0);
    __syncthreads();
    for (int kt = 0; kt < nk; kt++) {
        int buf = kt & 1;
        if (kt + 1 < nk) loadG((kt + 1) * 16);
        compute(buf);
        if (kt + 1 < nk) stage(buf ^ 1);
        __syncthreads();
    }

    // ---- epilogue ----
#pragma unroll
    for (int mf = 0; mf < MFRAG; mf++) {
#pragma unroll
        for (int nf = 0; nf < NFRAG; nf++) {
            const int col = bn0 + wn * WTN + nf * 8 + 2 * tg;
            const int r0  = bm0 + wm * WTM + mf * 16 + g;
#pragma unroll
            for (int half = 0; half < 2; half++) {
                const int row = r0 + half * 8;
                float v0 = c[mf][nf][half * 2 + 0];
                float v1 = c[mf][nf][half * 2 + 1];
                if (!BE2) { v0 += bias[col]; v1 += bias[col + 1]; }
                if (ACT == 1) {
                    v0 = 1.0f / (1.0f + expf(-v0));
                    v1 = 1.0f / (1.0f + expf(-v1));
                } else if (ACT == 2) {
                    v0 = fmaxf(v0, 0.0f);
                    v1 = fmaxf(v1, 0.0f);
                }
                if (GCOL) {
                    float gv = gates[(size_t)row * EEXP + (col >> 10)];
                    v0 *= gv; v1 *= gv;
                }
                if (BE2) {
                    float s0 = 0.0f, s1 = 0.0f;
#pragma unroll
                    for (int e = 0; e < EEXP; e++) {
                        float gv = gates[(size_t)row * EEXP + e];
                        s0 = fmaf(gv, be2[e * MDIM + col],     s0);
                        s1 = fmaf(gv, be2[e * MDIM + col + 1], s1);
                    }
                    v0 += s0; v1 += s1;
                }
                *(float2*)&C[(size_t)row * Hout + col] = make_float2(v0, v1);
            }
        }
    }
}

// ---------------------------------------------------------------------------
// Router: hid = tanh(cont @ rW1 + rb1); logits = hid @ rW2 + rb2;
// softmax -> top-2 -> renormalize -> dense gates (N, 8)
// ---------------------------------------------------------------------------
__global__ void router_kernel(const float* __restrict__ cont,
                              const float* __restrict__ rW1, const float* __restrict__ rb1,
                              const float* __restrict__ rW2, const float* __restrict__ rb2,
                              float* __restrict__ gates)
{
    __shared__ float cs[64];
    __shared__ float hid[64];
    __shared__ float logit[8];
    const int n = blockIdx.x;
    const int t = threadIdx.x;

    cs[t] = cont[(size_t)n * MDIM + t];
    __syncthreads();

    float a = rb1[t];
#pragma unroll
    for (int m = 0; m < 64; m++) a = fmaf(cs[m], rW1[m * 64 + t], a);
    hid[t] = tanhf(a);
    __syncthreads();

    if (t < EEXP) {
        float l = rb2[t];
#pragma unroll
        for (int j = 0; j < 64; j++) l = fmaf(hid[j], rW2[j * EEXP + t], l);
        logit[t] = l;
    }
    __syncthreads();

    if (t == 0) {
        float mx = logit[0];
        for (int e = 1; e < EEXP; e++) mx = fmaxf(mx, logit[e]);
        float p[EEXP];
        for (int e = 0; e < EEXP; e++) p[e] = expf(logit[e] - mx);
        int i1 = 0;
        for (int e = 1; e < EEXP; e++) if (p[e] > p[i1]) i1 = e;
        int i2 = (i1 == 0) ? 1 : 0;
        for (int e = 0; e < EEXP; e++) if (e != i1 && p[e] > p[i2]) i2 = e;
        float denom = p[i1] + p[i2];
        float gg[EEXP];
        for (int e = 0; e < EEXP; e++) gg[e] = 0.0f;
        gg[i1] = p[i1] / denom;
        gg[i2] = p[i2] / denom;
        for (int e = 0; e < EEXP; e++) gates[(size_t)n * EEXP + e] = gg[e];
    }
}

// ---------------------------------------------------------------------------
// LayerNorm over D=1024, one block (256 threads) per row.
// ---------------------------------------------------------------------------
__global__ void layernorm_kernel(const float* __restrict__ x,
                                 const float* __restrict__ g, const float* __restrict__ b,
                                 float* __restrict__ out)
{
    const int n = blockIdx.x;
    const int t = threadIdx.x;
    const float* row = x + (size_t)n * DDIM;

    float v[4];
    float s = 0.0f, s2 = 0.0f;
#pragma unroll
    for (int i = 0; i < 4; i++) {
        v[i] = row[t + i * 256];
        s += v[i];
        s2 += v[i] * v[i];
    }
#pragma unroll
    for (int o = 16; o > 0; o >>= 1) {
        s  += __shfl_xor_sync(0xFFFFFFFFu, s, o);
        s2 += __shfl_xor_sync(0xFFFFFFFFu, s2, o);
    }
    __shared__ float sh1[8], sh2[8];
    __shared__ float mu_s, rstd_s;
    const int warp = t >> 5, lane = t & 31;
    if (lane == 0) { sh1[warp] = s; sh2[warp] = s2; }
    __syncthreads();
    if (t == 0) {
        float S = 0.0f, S2 = 0.0f;
        for (int wq = 0; wq < 8; wq++) { S += sh1[wq]; S2 += sh2[wq]; }
        float mu  = S / (float)DDIM;
        float var = S2 / (float)DDIM - mu * mu;
        mu_s   = mu;
        rstd_s = rsqrtf(var + 1e-5f);
    }
    __syncthreads();
    const float mu = mu_s, rstd = rstd_s;
    float* orow = out + (size_t)n * DDIM;
#pragma unroll
    for (int i = 0; i < 4; i++) {
        int col = t + i * 256;
        orow[col] = (v[i] - mu) * rstd * g[col] + b[col];
    }
}

// ---------------------------------------------------------------------------
// kernel_launch
// ---------------------------------------------------------------------------
extern "C" void kernel_launch(void* const* d_in, const int* in_sizes, int n_in,
                              void* d_out, int out_size)
{
    const float* X     = (const float*)d_in[0];
    const float* enc_W = (const float*)d_in[1];
    const float* enc_b = (const float*)d_in[2];
    const float* s2c_W = (const float*)d_in[3];
    const float* s2c_b = (const float*)d_in[4];
    const float* rW1   = (const float*)d_in[5];
    const float* rb1   = (const float*)d_in[6];
    const float* rW2   = (const float*)d_in[7];
    const float* rb2   = (const float*)d_in[8];
    const float* We1   = (const float*)d_in[9];
    const float* be1   = (const float*)d_in[10];
    const float* We2   = (const float*)d_in[11];
    const float* be2   = (const float*)d_in[12];
    const float* c2s_W = (const float*)d_in[13];
    const float* c2s_b = (const float*)d_in[14];
    const float* dec_W = (const float*)d_in[15];
    const float* dec_b = (const float*)d_in[16];
    const float* ln_g  = (const float*)d_in[17];
    const float* ln_b  = (const float*)d_in[18];

    float *spk_enc, *cont, *gates, *hbig, *outflat, *spk_moe, *decoded;
    cudaGetSymbolAddress((void**)&spk_enc, g_spk_enc);
    cudaGetSymbolAddress((void**)&cont,    g_cont);
    cudaGetSymbolAddress((void**)&gates,   g_gates);
    cudaGetSymbolAddress((void**)&hbig,    g_hbig);
    cudaGetSymbolAddress((void**)&outflat, g_outflat);
    cudaGetSymbolAddress((void**)&spk_moe, g_spk_moe);
    cudaGetSymbolAddress((void**)&decoded, g_decoded);

    // Config A: 128x128 tile, 8 warps (2x4), warp tile 64x32
    // Config B: 64x64 tile, 4 warps (2x2), warp tile 32x32
    // 1) encoder: spikes_enc = sigmoid(X @ enc_W + enc_b)       8192x1024 @ 1024x2048
    mma_gemm<128, 128, 2, 4, 4, 4, 1, false, false, false>
        <<<dim3(HDIM / 128, NTOK / 128), 256>>>(X, enc_W, enc_b, spk_enc,
                                                DDIM, HDIM, nullptr, nullptr);

    // 2) s2c: cont = spikes_enc @ s2c_W + s2c_b                 8192x2048 @ 2048x64
    mma_gemm<64, 64, 2, 2, 2, 4, 0, false, false, false>
        <<<dim3(1, NTOK / 64), 128>>>(spk_enc, s2c_W, s2c_b, cont,
                                      HDIM, MDIM, nullptr, nullptr);

    // 3) router -> dense gates (8192 x 8)
    router_kernel<<<NTOK, 64>>>(cont, rW1, rb1, rW2, rb2, gates);

    // 4a) hbig[n, e*1024+h] = gates[n,e] * relu(cont @ We1_e + be1_e)
    //     one GEMM: 8192x64 @ 64x8192 (expert-strided B, gate in epilogue)
    mma_gemm<128, 128, 2, 4, 4, 4, 2, true, true, false>
        <<<dim3(HBIG / 128, NTOK / 128), 256>>>(cont, We1, be1, hbig,
                                                MDIM, HBIG, gates, nullptr);

    // 4b) outflat = hbig @ We2(viewed 8192x64) + sum_e g_e*be2_e   8192x8192 @ 8192x64
    mma_gemm<64, 64, 2, 2, 2, 4, 0, false, false, true>
        <<<dim3(1, NTOK / 64), 128>>>(hbig, We2, nullptr, outflat,
                                      HBIG, MDIM, gates, be2);

    // 5) c2s: spikes_moe = sigmoid(outflat @ c2s_W + c2s_b)     8192x64 @ 64x2048
    mma_gemm<128, 128, 2, 4, 4, 4, 1, false, false, false>
        <<<dim3(HDIM / 128, NTOK / 128), 256>>>(outflat, c2s_W, c2s_b, spk_moe,
                                                MDIM, HDIM, nullptr, nullptr);

    // 6) decoder: decoded = sigmoid(spikes_moe @ dec_W + dec_b) 8192x2048 @ 2048x1024
    mma_gemm<128, 128, 2, 4, 4, 4, 1, false, false, false>
        <<<dim3(DDIM / 128, NTOK / 128), 256>>>(spk_moe, dec_W, dec_b, decoded,
                                                HDIM, DDIM, nullptr, nullptr);

    // 7) layernorm -> d_out
    layernorm_kernel<<<NTOK, 256>>>(decoded, ln_g, ln_b, (float*)d_out);
}

// round 3
// speedup vs baseline: 4.3276x; 1.7747x over previous
#include <cuda_runtime.h>
#include <math.h>

// Problem dims
#define NTOK 8192
#define DDIM 1024
#define HDIM 2048
#define MDIM 64
#define EEXP 8
#define HHALF 1024
#define ECAP 8192          // per-expert capacity (top-2 distinct => <= NTOK)
#define S2C_SPLIT 4

// ---------------------------------------------------------------------------
// Scratch (device globals)
// ---------------------------------------------------------------------------
__device__ float g_spk_enc[(size_t)NTOK * HDIM];
__device__ float g_part_s2c[(size_t)S2C_SPLIT * NTOK * MDIM];
__device__ float g_cont[(size_t)NTOK * MDIM];
__device__ int   g_assign_e[NTOK * 2];
__device__ float g_assign_w[NTOK * 2];
__device__ int   g_count[EEXP];
__device__ int   g_bucket[EEXP * ECAP];
__device__ float g_hspar[(size_t)EEXP * ECAP * HHALF];   // 256MB
__device__ float g_part[(size_t)NTOK * 2 * MDIM];
__device__ float g_outflat[(size_t)NTOK * MDIM];
__device__ float g_spk_moe[(size_t)NTOK * HDIM];
__device__ float g_decoded[(size_t)NTOK * DDIM];

__device__ __forceinline__ unsigned f2tf(float x) {
    unsigned u;
    asm("cvt.rna.tf32.f32 %0, %1;" : "=r"(u) : "f"(x));
    return u;
}
__device__ __forceinline__ void cp16(void* dst, const void* src) {
    unsigned d = (unsigned)__cvta_generic_to_shared(dst);
    asm volatile("cp.async.cg.shared.global [%0], [%1], 16;\n" :: "r"(d), "l"(src));
}
__device__ __forceinline__ void cp_commit() {
    asm volatile("cp.async.commit_group;\n");
}
template<int N> __device__ __forceinline__ void cp_wait() {
    asm volatile("cp.async.wait_group %0;\n" :: "n"(N));
}

// ---------------------------------------------------------------------------
// Multistage tf32 GEMM: C[N x Hout] = epi(A[N x K] @ W[K x Hout] + bias)
// BK=16. fp32 staged in smem via cp.async; cvt.rna.tf32 at fragment read.
// Modes:
//   ACT: 0=none 1=sigmoid 2=relu
//   SPLITZ: blockIdx.z = K-split index (A col offset z*Kloop, C += z*c_zstride)
//   EXP1: blockIdx.z = expert; A rows gathered via bucket; W=We1_e, bias=be1_e,
//         C=hspar_e; early-exit + masked store on count[e]
//   EXP2: blockIdx.z = expert; A=hspar_e; W=We2_e; epilogue scatters
//         w * value to part[assign*64 + col]; early-exit on count[e]
// ---------------------------------------------------------------------------
template<int BM, int BN, int WM, int WN, int MFRAG, int NFRAG, int STAGES,
         int ACT, bool SPLITZ, bool EXP1, bool EXP2, int MAXB>
__global__ __launch_bounds__(WM * WN * 32, MAXB)
void mma_gemm(const float* __restrict__ A, const float* __restrict__ W,
              const float* __restrict__ bias, float* __restrict__ C,
              int Kloop, int lda, int Hout, size_t c_zstride,
              const int* __restrict__ bucket, const float* __restrict__ aw,
              const int* __restrict__ count)
{
    constexpr int THREADS = WM * WN * 32;
    constexpr int AS = 20;              // A smem row stride (floats)
    constexpr int BS = BN + 8;          // B smem row stride (floats)
    constexpr int WTM = MFRAG * 16;
    constexpr int WTN = NFRAG * 8;
    constexpr int ALD = (BM * 16) / (THREADS * 4);
    constexpr int BLD = (16 * BN) / (THREADS * 4);

    extern __shared__ float dynsmem[];
    float* As = dynsmem;                        // [STAGES][BM*AS]
    float* Bs = dynsmem + (size_t)STAGES * BM * AS;  // [STAGES][16*BS]

    const int tid  = threadIdx.x;
    const int lane = tid & 31;
    const int w    = tid >> 5;
    const int g    = lane >> 2;
    const int tg   = lane & 3;
    const int wm   = w / WN;
    const int wn   = w % WN;
    const int bm0  = blockIdx.y * BM;
    const int bn0  = blockIdx.x * BN;
    const int e    = (EXP1 || EXP2) ? blockIdx.z : 0;

    int cnt = 0;
    if (EXP1 || EXP2) {
        cnt = count[e];
        if (bm0 >= cnt) return;
    }

    const float* Wp    = W;
    const float* biasp = bias;
    const float* Ap    = A;
    float*       Cp    = C;
    int kbase = 0;
    if (SPLITZ) { kbase = blockIdx.z * Kloop; Cp = C + (size_t)blockIdx.z * c_zstride; }
    if (EXP1)   { Wp = W + (size_t)e * MDIM * HHALF; biasp = bias + (size_t)e * HHALF;
                  Cp = C + (size_t)e * ECAP * HHALF; }
    if (EXP2)   { Wp = W + (size_t)e * HHALF * MDIM; Ap = A + (size_t)e * ECAP * HHALF; }

    // Per-thread A row base offsets (gathered for EXP1)
    size_t aoff[ALD];
#pragma unroll
    for (int it = 0; it < ALD; it++) {
        int idx  = tid + it * THREADS;
        int r    = idx >> 2;
        int grow = bm0 + r;
        if (EXP1) {
            int rr  = (grow < cnt) ? grow : (cnt - 1);
            int tok = bucket[e * ECAP + rr] >> 1;
            aoff[it] = (size_t)tok * MDIM;
        } else {
            aoff[it] = (size_t)grow * lda + kbase;
        }
    }

    float c[MFRAG][NFRAG][4];
#pragma unroll
    for (int i = 0; i < MFRAG; i++)
#pragma unroll
        for (int j = 0; j < NFRAG; j++)
#pragma unroll
            for (int q = 0; q < 4; q++) c[i][j][q] = 0.0f;

    const int nk = Kloop / 16;

    auto issue = [&](int st, int kt) {
        const int k0 = kt * 16;
        float* as = As + (size_t)st * BM * AS;
        float* bs = Bs + (size_t)st * 16 * BS;
#pragma unroll
        for (int it = 0; it < ALD; it++) {
            int idx = tid + it * THREADS;
            int r   = idx >> 2;
            int c4  = idx & 3;
            cp16(&as[r * AS + c4 * 4], Ap + aoff[it] + k0 + c4 * 4);
        }
#pragma unroll
        for (int it = 0; it < BLD; it++) {
            int idx = tid + it * THREADS;
            int r   = idx / (BN / 4);
            int c4  = idx % (BN / 4);
            cp16(&bs[r * BS + c4 * 4],
                 Wp + (size_t)(kbase + k0 + r) * Hout + bn0 + c4 * 4);
        }
    };

    // Prologue: fill STAGES-1 stages
#pragma unroll
    for (int s = 0; s < STAGES - 1; s++) {
        if (s < nk) issue(s, s);
        cp_commit();
    }

    for (int kt = 0; kt < nk; kt++) {
        cp_wait<STAGES - 2>();
        __syncthreads();
        const int st = kt % STAGES;
        const float* as = As + (size_t)st * BM * AS;
        const float* bs = Bs + (size_t)st * 16 * BS;

#pragma unroll
        for (int ks = 0; ks < 2; ks++) {
            unsigned a[MFRAG][4], b[NFRAG][2];
#pragma unroll
            for (int mf = 0; mf < MFRAG; mf++) {
                const int m0 = wm * WTM + mf * 16;
                a[mf][0] = f2tf(as[(m0 + g)     * AS + ks * 8 + tg]);
                a[mf][1] = f2tf(as[(m0 + g + 8) * AS + ks * 8 + tg]);
                a[mf][2] = f2tf(as[(m0 + g)     * AS + ks * 8 + tg + 4]);
                a[mf][3] = f2tf(as[(m0 + g + 8) * AS + ks * 8 + tg + 4]);
            }
#pragma unroll
            for (int nf = 0; nf < NFRAG; nf++) {
                const int n0 = wn * WTN + nf * 8 + g;
                b[nf][0] = f2tf(bs[(ks * 8 + tg)     * BS + n0]);
                b[nf][1] = f2tf(bs[(ks * 8 + tg + 4) * BS + n0]);
            }
#pragma unroll
            for (int mf = 0; mf < MFRAG; mf++)
#pragma unroll
                for (int nf = 0; nf < NFRAG; nf++) {
                    asm volatile(
                        "mma.sync.aligned.m16n8k8.row.col.f32.tf32.tf32.f32 "
                        "{%0,%1,%2,%3}, {%4,%5,%6,%7}, {%8,%9}, {%0,%1,%2,%3};\n"
                        : "+f"(c[mf][nf][0]), "+f"(c[mf][nf][1]),
                          "+f"(c[mf][nf][2]), "+f"(c[mf][nf][3])
                        : "r"(a[mf][0]), "r"(a[mf][1]), "r"(a[mf][2]), "r"(a[mf][3]),
                          "r"(b[nf][0]), "r"(b[nf][1]));
                }
        }

        const int nxt = kt + STAGES - 1;
        if (nxt < nk) {
            __syncthreads();     // ensure all warps done reading stage being overwritten
            issue(nxt % STAGES, nxt);
        }
        cp_commit();
    }

    // ---- epilogue ----
#pragma unroll
    for (int mf = 0; mf < MFRAG; mf++) {
#pragma unroll
        for (int nf = 0; nf < NFRAG; nf++) {
            const int col = bn0 + wn * WTN + nf * 8 + 2 * tg;
            const int r0  = bm0 + wm * WTM + mf * 16 + g;
#pragma unroll
            for (int half = 0; half < 2; half++) {
                const int row = r0 + half * 8;
                float v0 = c[mf][nf][half * 2 + 0];
                float v1 = c[mf][nf][half * 2 + 1];
                if (EXP2) {
                    if (row < cnt) {
                        const int i  = bucket[e * ECAP + row];
                        const float wg = aw[i];
                        *(float2*)&Cp[(size_t)i * MDIM + col] =
                            make_float2(wg * v0, wg * v1);
                    }
                } else if (EXP1) {
                    if (row < cnt) {
                        v0 = fmaxf(v0 + biasp[col],     0.0f);
                        v1 = fmaxf(v1 + biasp[col + 1], 0.0f);
                        *(float2*)&Cp[(size_t)row * Hout + col] = make_float2(v0, v1);
                    }
                } else if (SPLITZ) {
                    *(float2*)&Cp[(size_t)row * Hout + col] = make_float2(v0, v1);
                } else {
                    v0 += biasp[col];
                    v1 += biasp[col + 1];
                    if (ACT == 1) {
                        v0 = 1.0f / (1.0f + expf(-v0));
                        v1 = 1.0f / (1.0f + expf(-v1));
                    } else if (ACT == 2) {
                        v0 = fmaxf(v0, 0.0f);
                        v1 = fmaxf(v1, 0.0f);
                    }
                    *(float2*)&Cp[(size_t)row * Hout + col] = make_float2(v0, v1);
                }
            }
        }
    }
}

// ---------------------------------------------------------------------------
// zero per-expert counts
// ---------------------------------------------------------------------------
__global__ void zero_counts() {
    if (threadIdx.x < EEXP) g_count[threadIdx.x] = 0;
}

// ---------------------------------------------------------------------------
// Router: reduce s2c split-K partials + bias -> cont; 2-layer router;
// softmax -> top-2 -> renormalize; emit assignments + bucket slots.
// One block (64 threads) per token.
// ---------------------------------------------------------------------------
__global__ void router_kernel(const float* __restrict__ part_s2c,
                              const float* __restrict__ s2c_b,
                              float* __restrict__ cont,
                              const float* __restrict__ rW1, const float* __restrict__ rb1,
                              const float* __restrict__ rW2, const float* __restrict__ rb2,
                              int* __restrict__ assign_e, float* __restrict__ assign_w)
{
    __shared__ float cs[64];
    __shared__ float hid[64];
    __shared__ float logit[8];
    const int n = blockIdx.x;
    const int t = threadIdx.x;

    float cv = s2c_b[t];
#pragma unroll
    for (int s = 0; s < S2C_SPLIT; s++)
        cv += part_s2c[(size_t)s * NTOK * MDIM + (size_t)n * MDIM + t];
    cont[(size_t)n * MDIM + t] = cv;
    cs[t] = cv;
    __syncthreads();

    float a = rb1[t];
#pragma unroll
    for (int m = 0; m < 64; m++) a = fmaf(cs[m], rW1[m * 64 + t], a);
    hid[t] = tanhf(a);
    __syncthreads();

    if (t < EEXP) {
        float l = rb2[t];
#pragma unroll
        for (int j = 0; j < 64; j++) l = fmaf(hid[j], rW2[j * EEXP + t], l);
        logit[t] = l;
    }
    __syncthreads();

    if (t == 0) {
        float mx = logit[0];
        for (int e = 1; e < EEXP; e++) mx = fmaxf(mx, logit[e]);
        float p[EEXP];
        for (int e = 0; e < EEXP; e++) p[e] = expf(logit[e] - mx);
        int i1 = 0;
        for (int e = 1; e < EEXP; e++) if (p[e] > p[i1]) i1 = e;
        int i2 = (i1 == 0) ? 1 : 0;
        for (int e = 0; e < EEXP; e++) if (e != i1 && p[e] > p[i2]) i2 = e;
        const float denom = p[i1] + p[i2];
        const int   ids[2] = {i1, i2};
        const float ws[2]  = {p[i1] / denom, p[i2] / denom};
#pragma unroll
        for (int k = 0; k < 2; k++) {
            const int i = n * 2 + k;
            assign_e[i] = ids[k];
            assign_w[i] = ws[k];
            const int slot = atomicAdd(&g_count[ids[k]], 1);
            g_bucket[ids[k] * ECAP + slot] = i;
        }
    }
}

// ---------------------------------------------------------------------------
// Combine: outflat[n] = part[2n] + part[2n+1] + w0*be2[e0] + w1*be2[e1]
// ---------------------------------------------------------------------------
__global__ void combine_kernel(const float* __restrict__ part,
                               const int* __restrict__ ae, const float* __restrict__ aw,
                               const float* __restrict__ be2,
                               float* __restrict__ outflat)
{
    const int i = blockIdx.x * 256 + threadIdx.x;   // over NTOK*64
    const int n = i >> 6;
    const int m = i & 63;
    const int e0 = ae[2 * n], e1 = ae[2 * n + 1];
    const float w0 = aw[2 * n], w1 = aw[2 * n + 1];
    outflat[i] = part[(size_t)(2 * n) * MDIM + m] + part[(size_t)(2 * n + 1) * MDIM + m]
               + w0 * be2[e0 * MDIM + m] + w1 * be2[e1 * MDIM + m];
}

// ---------------------------------------------------------------------------
// LayerNorm over D=1024, one block (256 threads) per row.
// ---------------------------------------------------------------------------
__global__ void layernorm_kernel(const float* __restrict__ x,
                                 const float* __restrict__ g, const float* __restrict__ b,
                                 float* __restrict__ out)
{
    const int n = blockIdx.x;
    const int t = threadIdx.x;
    const float* row = x + (size_t)n * DDIM;

    float v[4];
    float s = 0.0f, s2 = 0.0f;
#pragma unroll
    for (int i = 0; i < 4; i++) {
        v[i] = row[t + i * 256];
        s += v[i];
        s2 += v[i] * v[i];
    }
#pragma unroll
    for (int o = 16; o > 0; o >>= 1) {
        s  += __shfl_xor_sync(0xFFFFFFFFu, s, o);
        s2 += __shfl_xor_sync(0xFFFFFFFFu, s2, o);
    }
    __shared__ float sh1[8], sh2[8];
    __shared__ float mu_s, rstd_s;
    const int warp = t >> 5, lane = t & 31;
    if (lane == 0) { sh1[warp] = s; sh2[warp] = s2; }
    __syncthreads();
    if (t == 0) {
        float S = 0.0f, S2 = 0.0f;
        for (int wq = 0; wq < 8; wq++) { S += sh1[wq]; S2 += sh2[wq]; }
        float mu  = S / (float)DDIM;
        float var = S2 / (float)DDIM - mu * mu;
        mu_s   = mu;
        rstd_s = rsqrtf(var + 1e-5f);
    }
    __syncthreads();
    const float mu = mu_s, rstd = rstd_s;
    float* orow = out + (size_t)n * DDIM;
#pragma unroll
    for (int i = 0; i < 4; i++) {
        int col = t + i * 256;
        orow[col] = (v[i] - mu) * rstd * g[col] + b[col];
    }
}

// ---------------------------------------------------------------------------
// kernel_launch
// ---------------------------------------------------------------------------
// Instantiation aliases
#define CFG_BIG  128, 128, 2, 4, 4, 4, 4
#define CFG_SML  64, 64, 2, 2, 2, 4, 4
static constexpr int SMEM_BIG = 4 * (128 * 20 + 16 * (128 + 8)) * 4;  // 75776
static constexpr int SMEM_SML = 4 * (64 * 20 + 16 * (64 + 8)) * 4;    // 38912

extern "C" void kernel_launch(void* const* d_in, const int* in_sizes, int n_in,
                              void* d_out, int out_size)
{
    const float* X     = (const float*)d_in[0];
    const float* enc_W = (const float*)d_in[1];
    const float* enc_b = (const float*)d_in[2];
    const float* s2c_W = (const float*)d_in[3];
    const float* s2c_b = (const float*)d_in[4];
    const float* rW1   = (const float*)d_in[5];
    const float* rb1   = (const float*)d_in[6];
    const float* rW2   = (const float*)d_in[7];
    const float* rb2   = (const float*)d_in[8];
    const float* We1   = (const float*)d_in[9];
    const float* be1   = (const float*)d_in[10];
    const float* We2   = (const float*)d_in[11];
    const float* be2   = (const float*)d_in[12];
    const float* c2s_W = (const float*)d_in[13];
    const float* c2s_b = (const float*)d_in[14];
    const float* dec_W = (const float*)d_in[15];
    const float* dec_b = (const float*)d_in[16];
    const float* ln_g  = (const float*)d_in[17];
    const float* ln_b  = (const float*)d_in[18];

    float *spk_enc, *part_s2c, *cont, *aw, *hspar, *part, *outflat, *spk_moe, *decoded;
    int *ae, *bucket, *count;
    cudaGetSymbolAddress((void**)&spk_enc,  g_spk_enc);
    cudaGetSymbolAddress((void**)&part_s2c, g_part_s2c);
    cudaGetSymbolAddress((void**)&cont,     g_cont);
    cudaGetSymbolAddress((void**)&ae,       g_assign_e);
    cudaGetSymbolAddress((void**)&aw,       g_assign_w);
    cudaGetSymbolAddress((void**)&count,    g_count);
    cudaGetSymbolAddress((void**)&bucket,   g_bucket);
    cudaGetSymbolAddress((void**)&hspar,    g_hspar);
    cudaGetSymbolAddress((void**)&part,     g_part);
    cudaGetSymbolAddress((void**)&outflat,  g_outflat);
    cudaGetSymbolAddress((void**)&spk_moe,  g_spk_moe);
    cudaGetSymbolAddress((void**)&decoded,  g_decoded);

    auto kBig  = mma_gemm<CFG_BIG, 1, false, false, false, 2>;   // sigmoid
    auto kS2c  = mma_gemm<CFG_SML, 0, true,  false, false, 4>;   // split-K raw
    auto kExp1 = mma_gemm<CFG_BIG, 2, false, true,  false, 2>;   // gathered relu
    auto kExp2 = mma_gemm<CFG_SML, 0, false, false, true,  4>;   // scatter * w

    cudaFuncSetAttribute(kBig,  cudaFuncAttributeMaxDynamicSharedMemorySize, SMEM_BIG);
    cudaFuncSetAttribute(kS2c,  cudaFuncAttributeMaxDynamicSharedMemorySize, SMEM_SML);
    cudaFuncSetAttribute(kExp1, cudaFuncAttributeMaxDynamicSharedMemorySize, SMEM_BIG);
    cudaFuncSetAttribute(kExp2, cudaFuncAttributeMaxDynamicSharedMemorySize, SMEM_SML);

    // 1) encoder: sigmoid(X @ enc_W + enc_b)  (8192x1024 @ 1024x2048)
    kBig<<<dim3(HDIM / 128, NTOK / 128), 256, SMEM_BIG>>>(
        X, enc_W, enc_b, spk_enc, DDIM, DDIM, HDIM, 0, nullptr, nullptr, nullptr);

    // 2) s2c split-K=4: partials (8192x2048 @ 2048x64)
    kS2c<<<dim3(1, NTOK / 64, S2C_SPLIT), 128, SMEM_SML>>>(
        spk_enc, s2c_W, nullptr, part_s2c, HDIM / S2C_SPLIT, HDIM, MDIM,
        (size_t)NTOK * MDIM, nullptr, nullptr, nullptr);

    // 3) routing
    zero_counts<<<1, 32>>>();
    router_kernel<<<NTOK, 64>>>(part_s2c, s2c_b, cont, rW1, rb1, rW2, rb2, ae, aw);

    // 4a) per-expert hidden: relu(gather(cont) @ We1_e + be1_e)
    kExp1<<<dim3(HHALF / 128, ECAP / 128, EEXP), 256, SMEM_BIG>>>(
        cont, We1, be1, hspar, MDIM, MDIM, HHALF, 0, bucket, nullptr, count);

    // 4b) per-expert out: part[assign] = w * (h @ We2_e)
    kExp2<<<dim3(1, ECAP / 64, EEXP), 128, SMEM_SML>>>(
        hspar, We2, nullptr, part, HHALF, HHALF, MDIM, 0, bucket, aw, count);

    // 4c) combine assignments + be2
    combine_kernel<<<(NTOK * MDIM) / 256, 256>>>(part, ae, aw, be2, outflat);

    // 5) c2s: sigmoid(outflat @ c2s_W + c2s_b)  (8192x64 @ 64x2048)
    kBig<<<dim3(HDIM / 128, NTOK / 128), 256, SMEM_BIG>>>(
        outflat, c2s_W, c2s_b, spk_moe, MDIM, MDIM, HDIM, 0, nullptr, nullptr, nullptr);

    // 6) decoder: sigmoid(spk_moe @ dec_W + dec_b)  (8192x2048 @ 2048x1024)
    kBig<<<dim3(DDIM / 128, NTOK / 128), 256, SMEM_BIG>>>(
        spk_moe, dec_W, dec_b, decoded, HDIM, HDIM, DDIM, 0, nullptr, nullptr, nullptr);

    // 7) layernorm -> d_out
    layernorm_kernel<<<NTOK, 256>>>(decoded, ln_g, ln_b, (float*)d_out);
}

// round 4
// speedup vs baseline: 4.9353x; 1.1404x over previous
#include <cuda_runtime.h>
#include <math.h>

// Problem dims
#define NTOK 8192
#define DDIM 1024
#define HDIM 2048
#define MDIM 64
#define EEXP 8
#define HHALF 1024
#define ECAP 8192
#define NASSIGN (NTOK * 2)
#define S2C_SPLIT 16        // HDIM / 128
#define EXP_SPLIT 8         // HHALF / 128

// ---------------------------------------------------------------------------
// Scratch (device globals)
// ---------------------------------------------------------------------------
__device__ float g_part_s2c[(size_t)S2C_SPLIT * NTOK * MDIM];   // 33.5MB
__device__ float g_cont[(size_t)NTOK * MDIM];
__device__ int   g_assign_e[NASSIGN];
__device__ float g_assign_w[NASSIGN];
__device__ int   g_count[EEXP];
__device__ int   g_bucket[EEXP * ECAP];
__device__ float g_part_exp[(size_t)EXP_SPLIT * NASSIGN * MDIM]; // 33.5MB
__device__ float g_outflat[(size_t)NTOK * MDIM];
__device__ float g_spk_moe[(size_t)NTOK * HDIM];
__device__ float g_decoded[(size_t)NTOK * DDIM];

__device__ __forceinline__ unsigned f2tf(float x) {
    unsigned u;
    asm("cvt.rna.tf32.f32 %0, %1;" : "=r"(u) : "f"(x));
    return u;
}
__device__ __forceinline__ void cp16(void* dst, const void* src) {
    unsigned d = (unsigned)__cvta_generic_to_shared(dst);
    asm volatile("cp.async.cg.shared.global [%0], [%1], 16;\n" :: "r"(d), "l"(src));
}
__device__ __forceinline__ void cp_commit() {
    asm volatile("cp.async.commit_group;\n");
}
template<int N> __device__ __forceinline__ void cp_wait() {
    asm volatile("cp.async.wait_group %0;\n" :: "n"(N));
}

__device__ __forceinline__ void mma_tf32(float c[4], const unsigned a[4], const unsigned b[2]) {
    asm volatile(
        "mma.sync.aligned.m16n8k8.row.col.f32.tf32.tf32.f32 "
        "{%0,%1,%2,%3}, {%4,%5,%6,%7}, {%8,%9}, {%0,%1,%2,%3};\n"
        : "+f"(c[0]), "+f"(c[1]), "+f"(c[2]), "+f"(c[3])
        : "r"(a[0]), "r"(a[1]), "r"(a[2]), "r"(a[3]), "r"(b[0]), "r"(b[1]));
}

// Shared pipeline geometry (BM=128, BN=128, 8 warps 2x4, frag 4x4, 4 stages)
#define BM 128
#define BN 128
#define AS 20
#define BS1 136
#define STAGES 4
#define PIPE_FLOATS (STAGES * (BM * AS + 16 * BS1))    // 18944 floats = 75776B
#define SPIKE_S 132                                     // spike tile stride
#define W2_S 72                                         // W2 chunk stride
#define W2_OFF PIPE_FLOATS                              // W2 after pipeline
#define FUSED_SMEM ((PIPE_FLOATS + 128 * W2_S) * 4)     // 112640 B
#define PIPE_SMEM (PIPE_FLOATS * 4)                     // 75776 B

// ---------------------------------------------------------------------------
// Fused GEMM+GEMM: tile1 = act(A[128,K] @ W1[:,bn0:bn0+128] + b1) in smem,
// then part[128,64] = tile1 @ W2[bn0:bn0+128, :64], written as split-K partial.
//   EXPM=false: enc+s2c.  A rows direct, sigmoid, partial indexed by token row.
//   EXPM=true : exp1+exp2. blockIdx.z=expert, A rows gathered via bucket, relu,
//               partial scattered to assignment id, rows masked by count.
// ---------------------------------------------------------------------------
template<bool EXPM>
__global__ __launch_bounds__(256, 2)
void fused_gemm2(const float* __restrict__ A, const float* __restrict__ W1,
                 const float* __restrict__ b1, const float* __restrict__ W2,
                 float* __restrict__ Cpart, int K, int lda, int ldw1,
                 const int* __restrict__ bucket, const int* __restrict__ count)
{
    extern __shared__ float sm[];
    float* spike = sm;                // [128][SPIKE_S] (aliases pipeline)
    float* w2s   = sm + W2_OFF;       // [128][W2_S]

    const int tid  = threadIdx.x;
    const int lane = tid & 31;
    const int w    = tid >> 5;
    const int g    = lane >> 2;
    const int tg   = lane & 3;
    const int wm   = w >> 2;          // 0..1
    const int wn   = w & 3;           // 0..3
    const int bm0  = blockIdx.y * BM;
    const int bn0  = blockIdx.x * BN;
    const int e    = EXPM ? blockIdx.z : 0;

    int cnt = 0;
    if (EXPM) {
        cnt = count[e];
        if (bm0 >= cnt) return;
    }

    const float* W1p = EXPM ? W1 + (size_t)e * MDIM * HHALF : W1;
    const float* b1p = EXPM ? b1 + (size_t)e * HHALF : b1;
    const float* W2p = EXPM ? W2 + (size_t)e * HHALF * MDIM : W2;

    // Per-thread A row offsets (2 rows per thread: BM*16/4 f4 / 256 thr = 2 iters)
    constexpr int ALD = (BM * 16) / (256 * 4);
    constexpr int BLD = (16 * BN) / (256 * 4);
    size_t aoff[ALD];
#pragma unroll
    for (int it = 0; it < ALD; it++) {
        int idx  = tid + it * 256;
        int r    = idx >> 2;
        int grow = bm0 + r;
        if (EXPM) {
            int rr  = (grow < cnt) ? grow : (cnt - 1);
            int tok = bucket[e * ECAP + rr] >> 1;
            aoff[it] = (size_t)tok * MDIM;
        } else {
            aoff[it] = (size_t)grow * lda;
        }
    }

    // Prefetch W2 chunk [bn0..bn0+128) x 64 as its own first cp.async group
#pragma unroll
    for (int it = 0; it < (128 * 64) / (256 * 4); it++) {   // 8 iters
        int idx = tid + it * 256;
        int r   = idx >> 4;           // 16 f4 per row
        int c4  = idx & 15;
        cp16(&w2s[r * W2_S + c4 * 4], &W2p[(size_t)(bn0 + r) * MDIM + c4 * 4]);
    }
    cp_commit();

    float c[4][4][4];
#pragma unroll
    for (int i = 0; i < 4; i++)
#pragma unroll
        for (int j = 0; j < 4; j++)
#pragma unroll
            for (int q = 0; q < 4; q++) c[i][j][q] = 0.0f;

    const int nk = K / 16;
    auto issue = [&](int st, int kt) {
        const int k0 = kt * 16;
        float* as = sm + st * (BM * AS);
        float* bs = sm + STAGES * (BM * AS) + st * (16 * BS1);
#pragma unroll
        for (int it = 0; it < ALD; it++) {
            int idx = tid + it * 256;
            int r   = idx >> 2;
            int c4  = idx & 3;
            cp16(&as[r * AS + c4 * 4], A + aoff[it] + k0 + c4 * 4);
        }
#pragma unroll
        for (int it = 0; it < BLD; it++) {
            int idx = tid + it * 256;
            int r   = idx >> 5;       // 32 f4 per row
            int c4  = idx & 31;
            cp16(&bs[r * BS1 + c4 * 4],
                 &W1p[(size_t)(k0 + r) * ldw1 + bn0 + c4 * 4]);
        }
    };

#pragma unroll
    for (int s = 0; s < STAGES - 1; s++) {
        if (s < nk) issue(s, s);
        cp_commit();
    }

    for (int kt = 0; kt < nk; kt++) {
        cp_wait<STAGES - 2>();
        __syncthreads();
        const int st = kt % STAGES;
        const float* as = sm + st * (BM * AS);
        const float* bs = sm + STAGES * (BM * AS) + st * (16 * BS1);
#pragma unroll
        for (int ks = 0; ks < 2; ks++) {
            unsigned a[4][4], b[4][2];
#pragma unroll
            for (int mf = 0; mf < 4; mf++) {
                const int m0 = wm * 64 + mf * 16;
                a[mf][0] = f2tf(as[(m0 + g)     * AS + ks * 8 + tg]);
                a[mf][1] = f2tf(as[(m0 + g + 8) * AS + ks * 8 + tg]);
                a[mf][2] = f2tf(as[(m0 + g)     * AS + ks * 8 + tg + 4]);
                a[mf][3] = f2tf(as[(m0 + g + 8) * AS + ks * 8 + tg + 4]);
            }
#pragma unroll
            for (int nf = 0; nf < 4; nf++) {
                const int n0 = wn * 32 + nf * 8 + g;
                b[nf][0] = f2tf(bs[(ks * 8 + tg)     * BS1 + n0]);
                b[nf][1] = f2tf(bs[(ks * 8 + tg + 4) * BS1 + n0]);
            }
#pragma unroll
            for (int mf = 0; mf < 4; mf++)
#pragma unroll
                for (int nf = 0; nf < 4; nf++) mma_tf32(c[mf][nf], a[mf], b[nf]);
        }
        const int nxt = kt + STAGES - 1;
        if (nxt < nk) issue(nxt % STAGES, nxt);
        cp_commit();
    }

    // Drain everything (incl. W2 group), then write activated tile into smem
    cp_wait<0>();
    __syncthreads();
#pragma unroll
    for (int mf = 0; mf < 4; mf++) {
#pragma unroll
        for (int nf = 0; nf < 4; nf++) {
            const int col = wn * 32 + nf * 8 + 2 * tg;
            const int r0  = wm * 64 + mf * 16 + g;
#pragma unroll
            for (int half = 0; half < 2; half++) {
                const int row = r0 + half * 8;
                float v0 = c[mf][nf][half * 2 + 0] + b1p[bn0 + col];
                float v1 = c[mf][nf][half * 2 + 1] + b1p[bn0 + col + 1];
                if (EXPM) {
                    v0 = fmaxf(v0, 0.0f);
                    v1 = fmaxf(v1, 0.0f);
                } else {
                    v0 = 1.0f / (1.0f + expf(-v0));
                    v1 = 1.0f / (1.0f + expf(-v1));
                }
                *(float2*)&spike[row * SPIKE_S + col] = make_float2(v0, v1);
            }
        }
    }
    __syncthreads();

    // ---- second GEMM: part[128x64] = spike(128x128) @ w2s(128x64) ----
    const int wm2 = w >> 1;           // 0..3 (rows)
    const int wn2 = w & 1;            // 0..1 (cols)
    float c2[2][4][4];
#pragma unroll
    for (int i = 0; i < 2; i++)
#pragma unroll
        for (int j = 0; j < 4; j++)
#pragma unroll
            for (int q = 0; q < 4; q++) c2[i][j][q] = 0.0f;

#pragma unroll
    for (int ks = 0; ks < 16; ks++) {
        unsigned a[2][4], b[4][2];
#pragma unroll
        for (int mf = 0; mf < 2; mf++) {
            const int m0 = wm2 * 32 + mf * 16;
            a[mf][0] = f2tf(spike[(m0 + g)     * SPIKE_S + ks * 8 + tg]);
            a[mf][1] = f2tf(spike[(m0 + g + 8) * SPIKE_S + ks * 8 + tg]);
            a[mf][2] = f2tf(spike[(m0 + g)     * SPIKE_S + ks * 8 + tg + 4]);
            a[mf][3] = f2tf(spike[(m0 + g + 8) * SPIKE_S + ks * 8 + tg + 4]);
        }
#pragma unroll
        for (int nf = 0; nf < 4; nf++) {
            const int n0 = wn2 * 32 + nf * 8 + g;
            b[nf][0] = f2tf(w2s[(ks * 8 + tg)     * W2_S + n0]);
            b[nf][1] = f2tf(w2s[(ks * 8 + tg + 4) * W2_S + n0]);
        }
#pragma unroll
        for (int mf = 0; mf < 2; mf++)
#pragma unroll
            for (int nf = 0; nf < 4; nf++) mma_tf32(c2[mf][nf], a[mf], b[nf]);
    }

    // ---- write split-K partial ----
    const size_t split_base = (size_t)blockIdx.x * (EXPM ? NASSIGN : NTOK) * MDIM;
#pragma unroll
    for (int mf = 0; mf < 2; mf++) {
#pragma unroll
        for (int nf = 0; nf < 4; nf++) {
            const int col = wn2 * 32 + nf * 8 + 2 * tg;
            const int r0  = wm2 * 32 + mf * 16 + g;
#pragma unroll
            for (int half = 0; half < 2; half++) {
                const int row = r0 + half * 8;
                float v0 = c2[mf][nf][half * 2 + 0];
                float v1 = c2[mf][nf][half * 2 + 1];
                if (EXPM) {
                    if (bm0 + row < cnt) {
                        const int i = bucket[e * ECAP + bm0 + row];
                        *(float2*)&Cpart[split_base + (size_t)i * MDIM + col] =
                            make_float2(v0, v1);
                    }
                } else {
                    *(float2*)&Cpart[split_base + (size_t)(bm0 + row) * MDIM + col] =
                        make_float2(v0, v1);
                }
            }
        }
    }
}

// ---------------------------------------------------------------------------
// Plain multistage tf32 GEMM (c2s, decoder): C = act(A @ W + bias)
// ---------------------------------------------------------------------------
template<int ACT>
__global__ __launch_bounds__(256, 2)
void mma_gemm(const float* __restrict__ A, const float* __restrict__ W,
              const float* __restrict__ bias, float* __restrict__ C,
              int K, int Hout)
{
    extern __shared__ float sm[];
    const int tid  = threadIdx.x;
    const int lane = tid & 31;
    const int w    = tid >> 5;
    const int g    = lane >> 2;
    const int tg   = lane & 3;
    const int wm   = w >> 2;
    const int wn   = w & 3;
    const int bm0  = blockIdx.y * BM;
    const int bn0  = blockIdx.x * BN;

    constexpr int ALD = (BM * 16) / (256 * 4);
    constexpr int BLD = (16 * BN) / (256 * 4);

    float c[4][4][4];
#pragma unroll
    for (int i = 0; i < 4; i++)
#pragma unroll
        for (int j = 0; j < 4; j++)
#pragma unroll
            for (int q = 0; q < 4; q++) c[i][j][q] = 0.0f;

    const int nk = K / 16;
    auto issue = [&](int st, int kt) {
        const int k0 = kt * 16;
        float* as = sm + st * (BM * AS);
        float* bs = sm + STAGES * (BM * AS) + st * (16 * BS1);
#pragma unroll
        for (int it = 0; it < ALD; it++) {
            int idx = tid + it * 256;
            int r   = idx >> 2;
            int c4  = idx & 3;
            cp16(&as[r * AS + c4 * 4], &A[(size_t)(bm0 + r) * K + k0 + c4 * 4]);
        }
#pragma unroll
        for (int it = 0; it < BLD; it++) {
            int idx = tid + it * 256;
            int r   = idx >> 5;
            int c4  = idx & 31;
            cp16(&bs[r * BS1 + c4 * 4], &W[(size_t)(k0 + r) * Hout + bn0 + c4 * 4]);
        }
    };

#pragma unroll
    for (int s = 0; s < STAGES - 1; s++) {
        if (s < nk) issue(s, s);
        cp_commit();
    }

    for (int kt = 0; kt < nk; kt++) {
        cp_wait<STAGES - 2>();
        __syncthreads();
        const int st = kt % STAGES;
        const float* as = sm + st * (BM * AS);
        const float* bs = sm + STAGES * (BM * AS) + st * (16 * BS1);
#pragma unroll
        for (int ks = 0; ks < 2; ks++) {
            unsigned a[4][4], b[4][2];
#pragma unroll
            for (int mf = 0; mf < 4; mf++) {
                const int m0 = wm * 64 + mf * 16;
                a[mf][0] = f2tf(as[(m0 + g)     * AS + ks * 8 + tg]);
                a[mf][1] = f2tf(as[(m0 + g + 8) * AS + ks * 8 + tg]);
                a[mf][2] = f2tf(as[(m0 + g)     * AS + ks * 8 + tg + 4]);
                a[mf][3] = f2tf(as[(m0 + g + 8) * AS + ks * 8 + tg + 4]);
            }
#pragma unroll
            for (int nf = 0; nf < 4; nf++) {
                const int n0 = wn * 32 + nf * 8 + g;
                b[nf][0] = f2tf(bs[(ks * 8 + tg)     * BS1 + n0]);
                b[nf][1] = f2tf(bs[(ks * 8 + tg + 4) * BS1 + n0]);
            }
#pragma unroll
            for (int mf = 0; mf < 4; mf++)
#pragma unroll
                for (int nf = 0; nf < 4; nf++) mma_tf32(c[mf][nf], a[mf], b[nf]);
        }
        const int nxt = kt + STAGES - 1;
        if (nxt < nk) issue(nxt % STAGES, nxt);
        cp_commit();
    }

#pragma unroll
    for (int mf = 0; mf < 4; mf++) {
#pragma unroll
        for (int nf = 0; nf < 4; nf++) {
            const int col = bn0 + wn * 32 + nf * 8 + 2 * tg;
            const int r0  = bm0 + wm * 64 + mf * 16 + g;
#pragma unroll
            for (int half = 0; half < 2; half++) {
                const int row = r0 + half * 8;
                float v0 = c[mf][nf][half * 2 + 0] + bias[col];
                float v1 = c[mf][nf][half * 2 + 1] + bias[col + 1];
                if (ACT == 1) {
                    v0 = 1.0f / (1.0f + expf(-v0));
                    v1 = 1.0f / (1.0f + expf(-v1));
                }
                *(float2*)&C[(size_t)row * Hout + col] = make_float2(v0, v1);
            }
        }
    }
}

// ---------------------------------------------------------------------------
__global__ void zero_counts() {
    if (threadIdx.x < EEXP) g_count[threadIdx.x] = 0;
}

// Router: reduce 16 s2c partials + bias -> cont; router MLP; top-2; bucket.
__global__ void router_kernel(const float* __restrict__ part_s2c,
                              const float* __restrict__ s2c_b,
                              float* __restrict__ cont,
                              const float* __restrict__ rW1, const float* __restrict__ rb1,
                              const float* __restrict__ rW2, const float* __restrict__ rb2,
                              int* __restrict__ assign_e, float* __restrict__ assign_w)
{
    __shared__ float cs[64];
    __shared__ float hid[64];
    __shared__ float logit[8];
    const int n = blockIdx.x;
    const int t = threadIdx.x;

    float cv = s2c_b[t];
#pragma unroll
    for (int s = 0; s < S2C_SPLIT; s++)
        cv += part_s2c[(size_t)s * NTOK * MDIM + (size_t)n * MDIM + t];
    cont[(size_t)n * MDIM + t] = cv;
    cs[t] = cv;
    __syncthreads();

    float a = rb1[t];
#pragma unroll
    for (int m = 0; m < 64; m++) a = fmaf(cs[m], rW1[m * 64 + t], a);
    hid[t] = tanhf(a);
    __syncthreads();

    if (t < EEXP) {
        float l = rb2[t];
#pragma unroll
        for (int j = 0; j < 64; j++) l = fmaf(hid[j], rW2[j * EEXP + t], l);
        logit[t] = l;
    }
    __syncthreads();

    if (t == 0) {
        float mx = logit[0];
        for (int e = 1; e < EEXP; e++) mx = fmaxf(mx, logit[e]);
        float p[EEXP];
        for (int e = 0; e < EEXP; e++) p[e] = expf(logit[e] - mx);
        int i1 = 0;
        for (int e = 1; e < EEXP; e++) if (p[e] > p[i1]) i1 = e;
        int i2 = (i1 == 0) ? 1 : 0;
        for (int e = 0; e < EEXP; e++) if (e != i1 && p[e] > p[i2]) i2 = e;
        const float denom = p[i1] + p[i2];
        const int   ids[2] = {i1, i2};
        const float ws[2]  = {p[i1] / denom, p[i2] / denom};
#pragma unroll
        for (int k = 0; k < 2; k++) {
            const int i = n * 2 + k;
            assign_e[i] = ids[k];
            assign_w[i] = ws[k];
            const int slot = atomicAdd(&g_count[ids[k]], 1);
            g_bucket[ids[k] * ECAP + slot] = i;
        }
    }
}

// Combine: outflat[n,m] = sum_k w_k * (sum_split part_exp[s, 2n+k, m] + be2[e_k, m])
__global__ void combine_kernel(const float* __restrict__ part_exp,
                               const int* __restrict__ ae, const float* __restrict__ aw,
                               const float* __restrict__ be2,
                               float* __restrict__ outflat)
{
    const int i = blockIdx.x * 256 + threadIdx.x;
    const int n = i >> 6;
    const int m = i & 63;
    float acc = 0.0f;
#pragma unroll
    for (int k = 0; k < 2; k++) {
        const int idx = 2 * n + k;
        float s = be2[ae[idx] * MDIM + m];
#pragma unroll
        for (int sp = 0; sp < EXP_SPLIT; sp++)
            s += part_exp[(size_t)sp * NASSIGN * MDIM + (size_t)idx * MDIM + m];
        acc = fmaf(aw[idx], s, acc);
    }
    outflat[i] = acc;
}

// LayerNorm over D=1024
__global__ void layernorm_kernel(const float* __restrict__ x,
                                 const float* __restrict__ g, const float* __restrict__ b,
                                 float* __restrict__ out)
{
    const int n = blockIdx.x;
    const int t = threadIdx.x;
    const float* row = x + (size_t)n * DDIM;

    float v[4];
    float s = 0.0f, s2 = 0.0f;
#pragma unroll
    for (int i = 0; i < 4; i++) {
        v[i] = row[t + i * 256];
        s += v[i];
        s2 += v[i] * v[i];
    }
#pragma unroll
    for (int o = 16; o > 0; o >>= 1) {
        s  += __shfl_xor_sync(0xFFFFFFFFu, s, o);
        s2 += __shfl_xor_sync(0xFFFFFFFFu, s2, o);
    }
    __shared__ float sh1[8], sh2[8];
    __shared__ float mu_s, rstd_s;
    const int warp = t >> 5, lane = t & 31;
    if (lane == 0) { sh1[warp] = s; sh2[warp] = s2; }
    __syncthreads();
    if (t == 0) {
        float S = 0.0f, S2 = 0.0f;
        for (int wq = 0; wq < 8; wq++) { S += sh1[wq]; S2 += sh2[wq]; }
        float mu  = S / (float)DDIM;
        float var = S2 / (float)DDIM - mu * mu;
        mu_s   = mu;
        rstd_s = rsqrtf(var + 1e-5f);
    }
    __syncthreads();
    const float mu = mu_s, rstd = rstd_s;
    float* orow = out + (size_t)n * DDIM;
#pragma unroll
    for (int i = 0; i < 4; i++) {
        int col = t + i * 256;
        orow[col] = (v[i] - mu) * rstd * g[col] + b[col];
    }
}

// ---------------------------------------------------------------------------
extern "C" void kernel_launch(void* const* d_in, const int* in_sizes, int n_in,
                              void* d_out, int out_size)
{
    const float* X     = (const float*)d_in[0];
    const float* enc_W = (const float*)d_in[1];
    const float* enc_b = (const float*)d_in[2];
    const float* s2c_W = (const float*)d_in[3];
    const float* s2c_b = (const float*)d_in[4];
    const float* rW1   = (const float*)d_in[5];
    const float* rb1   = (const float*)d_in[6];
    const float* rW2   = (const float*)d_in[7];
    const float* rb2   = (const float*)d_in[8];
    const float* We1   = (const float*)d_in[9];
    const float* be1   = (const float*)d_in[10];
    const float* We2   = (const float*)d_in[11];
    const float* be2   = (const float*)d_in[12];
    const float* c2s_W = (const float*)d_in[13];
    const float* c2s_b = (const float*)d_in[14];
    const float* dec_W = (const float*)d_in[15];
    const float* dec_b = (const float*)d_in[16];
    const float* ln_g  = (const float*)d_in[17];
    const float* ln_b  = (const float*)d_in[18];

    float *part_s2c, *cont, *aw, *part_exp, *outflat, *spk_moe, *decoded;
    int *ae, *bucket, *count;
    cudaGetSymbolAddress((void**)&part_s2c, g_part_s2c);
    cudaGetSymbolAddress((void**)&cont,     g_cont);
    cudaGetSymbolAddress((void**)&ae,       g_assign_e);
    cudaGetSymbolAddress((void**)&aw,       g_assign_w);
    cudaGetSymbolAddress((void**)&count,    g_count);
    cudaGetSymbolAddress((void**)&bucket,   g_bucket);
    cudaGetSymbolAddress((void**)&part_exp, g_part_exp);
    cudaGetSymbolAddress((void**)&outflat,  g_outflat);
    cudaGetSymbolAddress((void**)&spk_moe,  g_spk_moe);
    cudaGetSymbolAddress((void**)&decoded,  g_decoded);

    auto kEnc = fused_gemm2<false>;
    auto kExp = fused_gemm2<true>;
    auto kSig = mma_gemm<1>;

    cudaFuncSetAttribute(kEnc, cudaFuncAttributeMaxDynamicSharedMemorySize, FUSED_SMEM);
    cudaFuncSetAttribute(kExp, cudaFuncAttributeMaxDynamicSharedMemorySize, FUSED_SMEM);
    cudaFuncSetAttribute(kSig, cudaFuncAttributeMaxDynamicSharedMemorySize, PIPE_SMEM);

    // 1) fused encoder+s2c: 16x64 CTAs, each writes a 128x64 split-K partial
    kEnc<<<dim3(S2C_SPLIT, NTOK / BM), 256, FUSED_SMEM>>>(
        X, enc_W, enc_b, s2c_W, part_s2c, DDIM, DDIM, HDIM, nullptr, nullptr);

    // 2) routing (reduces 16 partials)
    zero_counts<<<1, 32>>>();
    router_kernel<<<NTOK, 64>>>(part_s2c, s2c_b, cont, rW1, rb1, rW2, rb2, ae, aw);

    // 3) fused expert MLP: per expert, gathered GEMM1 + GEMM2 split-K partials
    kExp<<<dim3(EXP_SPLIT, ECAP / BM, EEXP), 256, FUSED_SMEM>>>(
        cont, We1, be1, We2, part_exp, MDIM, MDIM, HHALF, bucket, count);

    // 4) combine (reduces 8 partials x 2 assignments + be2)
    combine_kernel<<<(NTOK * MDIM) / 256, 256>>>(part_exp, ae, aw, be2, outflat);

    // 5) c2s: sigmoid(outflat @ c2s_W + c2s_b)   8192x64 @ 64x2048
    kSig<<<dim3(HDIM / BN, NTOK / BM), 256, PIPE_SMEM>>>(
        outflat, c2s_W, c2s_b, spk_moe, MDIM, HDIM);

    // 6) decoder: sigmoid(spk_moe @ dec_W + dec_b)   8192x2048 @ 2048x1024
    kSig<<<dim3(DDIM / BN, NTOK / BM), 256, PIPE_SMEM>>>(
        spk_moe, dec_W, dec_b, decoded, HDIM, DDIM);

    // 7) layernorm -> d_out
    layernorm_kernel<<<NTOK, 256>>>(decoded, ln_g, ln_b, (float*)d_out);
}

// round 5
// speedup vs baseline: 5.5952x; 1.1337x over previous
#include <cuda_runtime.h>
#include <math.h>

// Problem dims
#define NTOK 8192
#define DDIM 1024
#define HDIM 2048
#define MDIM 64
#define EEXP 8
#define HHALF 1024
#define ECAP 8192
#define NASSIGN (NTOK * 2)
#define S2C_SPLIT 16        // HDIM / 128
#define EXP_SPLIT 8         // HHALF / 128

// ---------------------------------------------------------------------------
// Scratch (device globals)
// ---------------------------------------------------------------------------
// tf32-rounded copies: [X | enc_W | s2c_W | We1 | We2 | c2s_W | dec_W]
#define RN_X   0UL
#define RN_EW  8388608UL
#define RN_SW  10485760UL
#define RN_W1  10616832UL
#define RN_W2  11141120UL
#define RN_CW  11665408UL
#define RN_DW  11796480UL
#define RN_TOT 13893632UL
__device__ float g_rnd[RN_TOT];

__device__ float g_part_s2c[(size_t)S2C_SPLIT * NTOK * MDIM];
__device__ float g_cont[(size_t)NTOK * MDIM];
__device__ int   g_assign_e[NASSIGN];
__device__ float g_assign_w[NASSIGN];
__device__ int   g_count[EEXP];
__device__ int   g_bucket[EEXP * ECAP];
__device__ float g_part_exp[(size_t)EXP_SPLIT * NASSIGN * MDIM];
__device__ float g_outflat[(size_t)NTOK * MDIM];
__device__ float g_spk_moe[(size_t)NTOK * HDIM];
__device__ float g_decoded[(size_t)NTOK * DDIM];

__device__ __forceinline__ unsigned f2tf(float x) {
    unsigned u;
    asm("cvt.rna.tf32.f32 %0, %1;" : "=r"(u) : "f"(x));
    return u;
}
__device__ __forceinline__ float rtf(float x) { return __uint_as_float(f2tf(x)); }
__device__ __forceinline__ void cp16(void* dst, const void* src) {
    unsigned d = (unsigned)__cvta_generic_to_shared(dst);
    asm volatile("cp.async.cg.shared.global [%0], [%1], 16;\n" :: "r"(d), "l"(src));
}
__device__ __forceinline__ void cp_commit() {
    asm volatile("cp.async.commit_group;\n");
}
template<int N> __device__ __forceinline__ void cp_wait() {
    asm volatile("cp.async.wait_group %0;\n" :: "n"(N));
}
__device__ __forceinline__ void mma_tf32(float c[4], const unsigned a[4], const unsigned b[2]) {
    asm volatile(
        "mma.sync.aligned.m16n8k8.row.col.f32.tf32.tf32.f32 "
        "{%0,%1,%2,%3}, {%4,%5,%6,%7}, {%8,%9}, {%0,%1,%2,%3};\n"
        : "+f"(c[0]), "+f"(c[1]), "+f"(c[2]), "+f"(c[3])
        : "r"(a[0]), "r"(a[1]), "r"(a[2]), "r"(a[3]), "r"(b[0]), "r"(b[1]));
}

// Geometry
#define BM 128
#define BN 128
#define AS 20
#define BS1 136
#define STAGES 4
#define PIPE_FLOATS (STAGES * (BM * AS + 16 * BS1))
#define SPIKE_S 132
#define W2_S 72
#define W2_OFF PIPE_FLOATS
#define FUSED_SMEM ((PIPE_FLOATS + 128 * W2_S) * 4)     // 112640 B

// Plain GEMM: BK=32, 3 stages
#define AS2 36
#define BS2 136
#define ST2 3
#define PIPE2_FLOATS (ST2 * (BM * AS2 + 32 * BS2))      // 26880
#define PIPE2_SMEM (PIPE2_FLOATS * 4)                   // 107520 B

// ---------------------------------------------------------------------------
// Pre-round X and all weights to tf32 (rna) into g_rnd; also zero counts.
// Destination is the contiguous g_rnd; sources selected by segment.
// ---------------------------------------------------------------------------
__global__ void round_all(const float* __restrict__ X,   const float* __restrict__ encW,
                          const float* __restrict__ s2cW, const float* __restrict__ We1,
                          const float* __restrict__ We2,  const float* __restrict__ c2sW,
                          const float* __restrict__ decW)
{
    if (blockIdx.x == 0 && threadIdx.x < EEXP) g_count[threadIdx.x] = 0;
    const size_t i = (size_t)blockIdx.x * 256 + threadIdx.x;   // float4 index
    const size_t f = i * 4;                                    // float index
    const float* src;
    size_t off;
    if      (f < RN_EW) { src = X;    off = f - RN_X;  }
    else if (f < RN_SW) { src = encW; off = f - RN_EW; }
    else if (f < RN_W1) { src = s2cW; off = f - RN_SW; }
    else if (f < RN_W2) { src = We1;  off = f - RN_W1; }
    else if (f < RN_CW) { src = We2;  off = f - RN_W2; }
    else if (f < RN_DW) { src = c2sW; off = f - RN_CW; }
    else                { src = decW; off = f - RN_DW; }
    float4 v = *(const float4*)&src[off];
    v.x = rtf(v.x); v.y = rtf(v.y); v.z = rtf(v.z); v.w = rtf(v.w);
    *(float4*)&g_rnd[f] = v;
}

// ---------------------------------------------------------------------------
// Fused GEMM+GEMM (inputs pre-rounded to tf32; raw-bit fragment reads).
//   EXPM=false: enc+s2c.   EXPM=true: expert MLP (gather/scatter).
// ---------------------------------------------------------------------------
template<bool EXPM>
__global__ __launch_bounds__(256, 2)
void fused_gemm2(const float* __restrict__ A, const float* __restrict__ W1,
                 const float* __restrict__ b1, const float* __restrict__ W2,
                 float* __restrict__ Cpart, int K, int lda, int ldw1,
                 const int* __restrict__ bucket, const int* __restrict__ count)
{
    extern __shared__ float sm[];
    float* spike = sm;
    float* w2s   = sm + W2_OFF;

    const int tid  = threadIdx.x;
    const int lane = tid & 31;
    const int w    = tid >> 5;
    const int g    = lane >> 2;
    const int tg   = lane & 3;
    const int wm   = w >> 2;
    const int wn   = w & 3;
    const int bm0  = blockIdx.y * BM;
    const int bn0  = blockIdx.x * BN;
    const int e    = EXPM ? blockIdx.z : 0;

    int cnt = 0;
    if (EXPM) {
        cnt = count[e];
        if (bm0 >= cnt) return;
    }

    const float* W1p = EXPM ? W1 + (size_t)e * MDIM * HHALF : W1;
    const float* b1p = EXPM ? b1 + (size_t)e * HHALF : b1;
    const float* W2p = EXPM ? W2 + (size_t)e * HHALF * MDIM : W2;

    constexpr int ALD = (BM * 16) / (256 * 4);
    constexpr int BLD = (16 * BN) / (256 * 4);
    size_t aoff[ALD];
#pragma unroll
    for (int it = 0; it < ALD; it++) {
        int idx  = tid + it * 256;
        int r    = idx >> 2;
        int grow = bm0 + r;
        if (EXPM) {
            int rr  = (grow < cnt) ? grow : (cnt - 1);
            int tok = bucket[e * ECAP + rr] >> 1;
            aoff[it] = (size_t)tok * MDIM;
        } else {
            aoff[it] = (size_t)grow * lda;
        }
    }

    // Prefetch W2 chunk as oldest cp.async group
#pragma unroll
    for (int it = 0; it < (128 * 64) / (256 * 4); it++) {
        int idx = tid + it * 256;
        int r   = idx >> 4;
        int c4  = idx & 15;
        cp16(&w2s[r * W2_S + c4 * 4], &W2p[(size_t)(bn0 + r) * MDIM + c4 * 4]);
    }
    cp_commit();

    float c[4][4][4];
#pragma unroll
    for (int i = 0; i < 4; i++)
#pragma unroll
        for (int j = 0; j < 4; j++)
#pragma unroll
            for (int q = 0; q < 4; q++) c[i][j][q] = 0.0f;

    const int nk = K / 16;
    auto issue = [&](int st, int kt) {
        const int k0 = kt * 16;
        float* as = sm + st * (BM * AS);
        float* bs = sm + STAGES * (BM * AS) + st * (16 * BS1);
#pragma unroll
        for (int it = 0; it < ALD; it++) {
            int idx = tid + it * 256;
            int r   = idx >> 2;
            int c4  = idx & 3;
            cp16(&as[r * AS + c4 * 4], A + aoff[it] + k0 + c4 * 4);
        }
#pragma unroll
        for (int it = 0; it < BLD; it++) {
            int idx = tid + it * 256;
            int r   = idx >> 5;
            int c4  = idx & 31;
            cp16(&bs[r * BS1 + c4 * 4],
                 &W1p[(size_t)(k0 + r) * ldw1 + bn0 + c4 * 4]);
        }
    };

#pragma unroll
    for (int s = 0; s < STAGES - 1; s++) {
        if (s < nk) issue(s, s);
        cp_commit();
    }

    for (int kt = 0; kt < nk; kt++) {
        cp_wait<STAGES - 2>();
        __syncthreads();
        const int st = kt % STAGES;
        const float* as = sm + st * (BM * AS);
        const float* bs = sm + STAGES * (BM * AS) + st * (16 * BS1);
#pragma unroll
        for (int ks = 0; ks < 2; ks++) {
            unsigned a[4][4], b[4][2];
#pragma unroll
            for (int mf = 0; mf < 4; mf++) {
                const int m0 = wm * 64 + mf * 16;
                a[mf][0] = __float_as_uint(as[(m0 + g)     * AS + ks * 8 + tg]);
                a[mf][1] = __float_as_uint(as[(m0 + g + 8) * AS + ks * 8 + tg]);
                a[mf][2] = __float_as_uint(as[(m0 + g)     * AS + ks * 8 + tg + 4]);
                a[mf][3] = __float_as_uint(as[(m0 + g + 8) * AS + ks * 8 + tg + 4]);
            }
#pragma unroll
            for (int nf = 0; nf < 4; nf++) {
                const int n0 = wn * 32 + nf * 8 + g;
                b[nf][0] = __float_as_uint(bs[(ks * 8 + tg)     * BS1 + n0]);
                b[nf][1] = __float_as_uint(bs[(ks * 8 + tg + 4) * BS1 + n0]);
            }
#pragma unroll
            for (int mf = 0; mf < 4; mf++)
#pragma unroll
                for (int nf = 0; nf < 4; nf++) mma_tf32(c[mf][nf], a[mf], b[nf]);
        }
        const int nxt = kt + STAGES - 1;
        if (nxt < nk) issue(nxt % STAGES, nxt);
        cp_commit();
    }

    cp_wait<0>();
    __syncthreads();
    // Activated tile -> smem, rounded to tf32 (bit-exact vs per-read cvt)
#pragma unroll
    for (int mf = 0; mf < 4; mf++) {
#pragma unroll
        for (int nf = 0; nf < 4; nf++) {
            const int col = wn * 32 + nf * 8 + 2 * tg;
            const int r0  = wm * 64 + mf * 16 + g;
#pragma unroll
            for (int half = 0; half < 2; half++) {
                const int row = r0 + half * 8;
                float v0 = c[mf][nf][half * 2 + 0] + b1p[bn0 + col];
                float v1 = c[mf][nf][half * 2 + 1] + b1p[bn0 + col + 1];
                if (EXPM) {
                    v0 = fmaxf(v0, 0.0f);
                    v1 = fmaxf(v1, 0.0f);
                } else {
                    v0 = 1.0f / (1.0f + expf(-v0));
                    v1 = 1.0f / (1.0f + expf(-v1));
                }
                *(float2*)&spike[row * SPIKE_S + col] = make_float2(rtf(v0), rtf(v1));
            }
        }
    }
    __syncthreads();

    // Second GEMM: part[128x64] = spike(128x128) @ w2s(128x64)
    const int wm2 = w >> 1;
    const int wn2 = w & 1;
    float c2[2][4][4];
#pragma unroll
    for (int i = 0; i < 2; i++)
#pragma unroll
        for (int j = 0; j < 4; j++)
#pragma unroll
            for (int q = 0; q < 4; q++) c2[i][j][q] = 0.0f;

#pragma unroll
    for (int ks = 0; ks < 16; ks++) {
        unsigned a[2][4], b[4][2];
#pragma unroll
        for (int mf = 0; mf < 2; mf++) {
            const int m0 = wm2 * 32 + mf * 16;
            a[mf][0] = __float_as_uint(spike[(m0 + g)     * SPIKE_S + ks * 8 + tg]);
            a[mf][1] = __float_as_uint(spike[(m0 + g + 8) * SPIKE_S + ks * 8 + tg]);
            a[mf][2] = __float_as_uint(spike[(m0 + g)     * SPIKE_S + ks * 8 + tg + 4]);
            a[mf][3] = __float_as_uint(spike[(m0 + g + 8) * SPIKE_S + ks * 8 + tg + 4]);
        }
#pragma unroll
        for (int nf = 0; nf < 4; nf++) {
            const int n0 = wn2 * 32 + nf * 8 + g;
            b[nf][0] = __float_as_uint(w2s[(ks * 8 + tg)     * W2_S + n0]);
            b[nf][1] = __float_as_uint(w2s[(ks * 8 + tg + 4) * W2_S + n0]);
        }
#pragma unroll
        for (int mf = 0; mf < 2; mf++)
#pragma unroll
            for (int nf = 0; nf < 4; nf++) mma_tf32(c2[mf][nf], a[mf], b[nf]);
    }

    const size_t split_base = (size_t)blockIdx.x * (EXPM ? NASSIGN : NTOK) * MDIM;
#pragma unroll
    for (int mf = 0; mf < 2; mf++) {
#pragma unroll
        for (int nf = 0; nf < 4; nf++) {
            const int col = wn2 * 32 + nf * 8 + 2 * tg;
            const int r0  = wm2 * 32 + mf * 16 + g;
#pragma unroll
            for (int half = 0; half < 2; half++) {
                const int row = r0 + half * 8;
                float v0 = c2[mf][nf][half * 2 + 0];
                float v1 = c2[mf][nf][half * 2 + 1];
                if (EXPM) {
                    if (bm0 + row < cnt) {
                        const int i = bucket[e * ECAP + bm0 + row];
                        *(float2*)&Cpart[split_base + (size_t)i * MDIM + col] =
                            make_float2(v0, v1);
                    }
                } else {
                    *(float2*)&Cpart[split_base + (size_t)(bm0 + row) * MDIM + col] =
                        make_float2(v0, v1);
                }
            }
        }
    }
}

// ---------------------------------------------------------------------------
// Plain multistage tf32 GEMM, BK=32, 3 stages. Sigmoid epilogue.
// ROUND=1: store tf32-rounded (feeds next GEMM). ROUND=0: store fp32.
// ---------------------------------------------------------------------------
template<int ROUND>
__global__ __launch_bounds__(256, 2)
void mma_gemm(const float* __restrict__ A, const float* __restrict__ W,
              const float* __restrict__ bias, float* __restrict__ C,
              int K, int Hout)
{
    extern __shared__ float sm[];
    const int tid  = threadIdx.x;
    const int lane = tid & 31;
    const int w    = tid >> 5;
    const int g    = lane >> 2;
    const int tg   = lane & 3;
    const int wm   = w >> 2;
    const int wn   = w & 3;
    const int bm0  = blockIdx.y * BM;
    const int bn0  = blockIdx.x * BN;

    constexpr int ALD = (BM * 32) / (256 * 4);   // 4
    constexpr int BLD = (32 * BN) / (256 * 4);   // 4

    float c[4][4][4];
#pragma unroll
    for (int i = 0; i < 4; i++)
#pragma unroll
        for (int j = 0; j < 4; j++)
#pragma unroll
            for (int q = 0; q < 4; q++) c[i][j][q] = 0.0f;

    const int nk = K / 32;
    auto issue = [&](int st, int kt) {
        const int k0 = kt * 32;
        float* as = sm + st * (BM * AS2);
        float* bs = sm + ST2 * (BM * AS2) + st * (32 * BS2);
#pragma unroll
        for (int it = 0; it < ALD; it++) {
            int idx = tid + it * 256;
            int r   = idx >> 3;           // 8 float4 per 32-wide row
            int c4  = idx & 7;
            cp16(&as[r * AS2 + c4 * 4], &A[(size_t)(bm0 + r) * K + k0 + c4 * 4]);
        }
#pragma unroll
        for (int it = 0; it < BLD; it++) {
            int idx = tid + it * 256;
            int r   = idx >> 5;           // 32 float4 per row
            int c4  = idx & 31;
            cp16(&bs[r * BS2 + c4 * 4], &W[(size_t)(k0 + r) * Hout + bn0 + c4 * 4]);
        }
    };

#pragma unroll
    for (int s = 0; s < ST2 - 1; s++) {
        if (s < nk) issue(s, s);
        cp_commit();
    }

    for (int kt = 0; kt < nk; kt++) {
        cp_wait<ST2 - 2>();
        __syncthreads();
        const int st = kt % ST2;
        const float* as = sm + st * (BM * AS2);
        const float* bs = sm + ST2 * (BM * AS2) + st * (32 * BS2);
#pragma unroll
        for (int ks = 0; ks < 4; ks++) {
            unsigned a[4][4], b[4][2];
#pragma unroll
            for (int mf = 0; mf < 4; mf++) {
                const int m0 = wm * 64 + mf * 16;
                a[mf][0] = __float_as_uint(as[(m0 + g)     * AS2 + ks * 8 + tg]);
                a[mf][1] = __float_as_uint(as[(m0 + g + 8) * AS2 + ks * 8 + tg]);
                a[mf][2] = __float_as_uint(as[(m0 + g)     * AS2 + ks * 8 + tg + 4]);
                a[mf][3] = __float_as_uint(as[(m0 + g + 8) * AS2 + ks * 8 + tg + 4]);
            }
#pragma unroll
            for (int nf = 0; nf < 4; nf++) {
                const int n0 = wn * 32 + nf * 8 + g;
                b[nf][0] = __float_as_uint(bs[(ks * 8 + tg)     * BS2 + n0]);
                b[nf][1] = __float_as_uint(bs[(ks * 8 + tg + 4) * BS2 + n0]);
            }
#pragma unroll
            for (int mf = 0; mf < 4; mf++)
#pragma unroll
                for (int nf = 0; nf < 4; nf++) mma_tf32(c[mf][nf], a[mf], b[nf]);
        }
        const int nxt = kt + ST2 - 1;
        if (nxt < nk) issue(nxt % ST2, nxt);
        cp_commit();
    }

#pragma unroll
    for (int mf = 0; mf < 4; mf++) {
#pragma unroll
        for (int nf = 0; nf < 4; nf++) {
            const int col = bn0 + wn * 32 + nf * 8 + 2 * tg;
            const int r0  = bm0 + wm * 64 + mf * 16 + g;
#pragma unroll
            for (int half = 0; half < 2; half++) {
                const int row = r0 + half * 8;
                float v0 = c[mf][nf][half * 2 + 0] + bias[col];
                float v1 = c[mf][nf][half * 2 + 1] + bias[col + 1];
                v0 = 1.0f / (1.0f + expf(-v0));
                v1 = 1.0f / (1.0f + expf(-v1));
                if (ROUND) { v0 = rtf(v0); v1 = rtf(v1); }
                *(float2*)&C[(size_t)row * Hout + col] = make_float2(v0, v1);
            }
        }
    }
}

// ---------------------------------------------------------------------------
// Router: reduce 16 s2c partials + bias -> cont (stored tf32-rounded);
// router MLP (fp32); top-2; bucket.
// ---------------------------------------------------------------------------
__global__ void router_kernel(const float* __restrict__ part_s2c,
                              const float* __restrict__ s2c_b,
                              float* __restrict__ cont,
                              const float* __restrict__ rW1, const float* __restrict__ rb1,
                              const float* __restrict__ rW2, const float* __restrict__ rb2,
                              int* __restrict__ assign_e, float* __restrict__ assign_w)
{
    __shared__ float cs[64];
    __shared__ float hid[64];
    __shared__ float logit[8];
    const int n = blockIdx.x;
    const int t = threadIdx.x;

    float cv = s2c_b[t];
#pragma unroll
    for (int s = 0; s < S2C_SPLIT; s++)
        cv += part_s2c[(size_t)s * NTOK * MDIM + (size_t)n * MDIM + t];
    cont[(size_t)n * MDIM + t] = rtf(cv);   // expert GEMM consumes tf32 bits
    cs[t] = cv;                              // router MLP uses full fp32
    __syncthreads();

    float a = rb1[t];
#pragma unroll
    for (int m = 0; m < 64; m++) a = fmaf(cs[m], rW1[m * 64 + t], a);
    hid[t] = tanhf(a);
    __syncthreads();

    if (t < EEXP) {
        float l = rb2[t];
#pragma unroll
        for (int j = 0; j < 64; j++) l = fmaf(hid[j], rW2[j * EEXP + t], l);
        logit[t] = l;
    }
    __syncthreads();

    if (t == 0) {
        float mx = logit[0];
        for (int e = 1; e < EEXP; e++) mx = fmaxf(mx, logit[e]);
        float p[EEXP];
        for (int e = 0; e < EEXP; e++) p[e] = expf(logit[e] - mx);
        int i1 = 0;
        for (int e = 1; e < EEXP; e++) if (p[e] > p[i1]) i1 = e;
        int i2 = (i1 == 0) ? 1 : 0;
        for (int e = 0; e < EEXP; e++) if (e != i1 && p[e] > p[i2]) i2 = e;
        const float denom = p[i1] + p[i2];
        const int   ids[2] = {i1, i2};
        const float ws[2]  = {p[i1] / denom, p[i2] / denom};
#pragma unroll
        for (int k = 0; k < 2; k++) {
            const int i = n * 2 + k;
            assign_e[i] = ids[k];
            assign_w[i] = ws[k];
            const int slot = atomicAdd(&g_count[ids[k]], 1);
            g_bucket[ids[k] * ECAP + slot] = i;
        }
    }
}

// Combine: outflat (tf32-rounded; consumed by c2s GEMM)
__global__ void combine_kernel(const float* __restrict__ part_exp,
                               const int* __restrict__ ae, const float* __restrict__ aw,
                               const float* __restrict__ be2,
                               float* __restrict__ outflat)
{
    const int i = blockIdx.x * 256 + threadIdx.x;
    const int n = i >> 6;
    const int m = i & 63;
    float acc = 0.0f;
#pragma unroll
    for (int k = 0; k < 2; k++) {
        const int idx = 2 * n + k;
        float s = be2[ae[idx] * MDIM + m];
#pragma unroll
        for (int sp = 0; sp < EXP_SPLIT; sp++)
            s += part_exp[(size_t)sp * NASSIGN * MDIM + (size_t)idx * MDIM + m];
        acc = fmaf(aw[idx], s, acc);
    }
    outflat[i] = rtf(acc);
}

// LayerNorm over D=1024
__global__ void layernorm_kernel(const float* __restrict__ x,
                                 const float* __restrict__ g, const float* __restrict__ b,
                                 float* __restrict__ out)
{
    const int n = blockIdx.x;
    const int t = threadIdx.x;
    const float* row = x + (size_t)n * DDIM;

    float v[4];
    float s = 0.0f, s2 = 0.0f;
#pragma unroll
    for (int i = 0; i < 4; i++) {
        v[i] = row[t + i * 256];
        s += v[i];
        s2 += v[i] * v[i];
    }
#pragma unroll
    for (int o = 16; o > 0; o >>= 1) {
        s  += __shfl_xor_sync(0xFFFFFFFFu, s, o);
        s2 += __shfl_xor_sync(0xFFFFFFFFu, s2, o);
    }
    __shared__ float sh1[8], sh2[8];
    __shared__ float mu_s, rstd_s;
    const int warp = t >> 5, lane = t & 31;
    if (lane == 0) { sh1[warp] = s; sh2[warp] = s2; }
    __syncthreads();
    if (t == 0) {
        float S = 0.0f, S2 = 0.0f;
        for (int wq = 0; wq < 8; wq++) { S += sh1[wq]; S2 += sh2[wq]; }
        float mu  = S / (float)DDIM;
        float var = S2 / (float)DDIM - mu * mu;
        mu_s   = mu;
        rstd_s = rsqrtf(var + 1e-5f);
    }
    __syncthreads();
    const float mu = mu_s, rstd = rstd_s;
    float* orow = out + (size_t)n * DDIM;
#pragma unroll
    for (int i = 0; i < 4; i++) {
        int col = t + i * 256;
        orow[col] = (v[i] - mu) * rstd * g[col] + b[col];
    }
}

// ---------------------------------------------------------------------------
extern "C" void kernel_launch(void* const* d_in, const int* in_sizes, int n_in,
                              void* d_out, int out_size)
{
    const float* X     = (const float*)d_in[0];
    const float* enc_W = (const float*)d_in[1];
    const float* enc_b = (const float*)d_in[2];
    const float* s2c_W = (const float*)d_in[3];
    const float* s2c_b = (const float*)d_in[4];
    const float* rW1   = (const float*)d_in[5];
    const float* rb1   = (const float*)d_in[6];
    const float* rW2   = (const float*)d_in[7];
    const float* rb2   = (const float*)d_in[8];
    const float* We1   = (const float*)d_in[9];
    const float* be1   = (const float*)d_in[10];
    const float* We2   = (const float*)d_in[11];
    const float* be2   = (const float*)d_in[12];
    const float* c2s_W = (const float*)d_in[13];
    const float* c2s_b = (const float*)d_in[14];
    const float* dec_W = (const float*)d_in[15];
    const float* dec_b = (const float*)d_in[16];
    const float* ln_g  = (const float*)d_in[17];
    const float* ln_b  = (const float*)d_in[18];

    float *rnd, *part_s2c, *cont, *aw, *part_exp, *outflat, *spk_moe, *decoded;
    int *ae, *bucket, *count;
    cudaGetSymbolAddress((void**)&rnd,      g_rnd);
    cudaGetSymbolAddress((void**)&part_s2c, g_part_s2c);
    cudaGetSymbolAddress((void**)&cont,     g_cont);
    cudaGetSymbolAddress((void**)&ae,       g_assign_e);
    cudaGetSymbolAddress((void**)&aw,       g_assign_w);
    cudaGetSymbolAddress((void**)&count,    g_count);
    cudaGetSymbolAddress((void**)&bucket,   g_bucket);
    cudaGetSymbolAddress((void**)&part_exp, g_part_exp);
    cudaGetSymbolAddress((void**)&outflat,  g_outflat);
    cudaGetSymbolAddress((void**)&spk_moe,  g_spk_moe);
    cudaGetSymbolAddress((void**)&decoded,  g_decoded);

    const float* Xr    = rnd + RN_X;
    const float* encWr = rnd + RN_EW;
    const float* s2cWr = rnd + RN_SW;
    const float* We1r  = rnd + RN_W1;
    const float* We2r  = rnd + RN_W2;
    const float* c2sWr = rnd + RN_CW;
    const float* decWr = rnd + RN_DW;

    auto kEnc = fused_gemm2<false>;
    auto kExp = fused_gemm2<true>;
    auto kC2s = mma_gemm<1>;
    auto kDec = mma_gemm<0>;

    cudaFuncSetAttribute(kEnc, cudaFuncAttributeMaxDynamicSharedMemorySize, FUSED_SMEM);
    cudaFuncSetAttribute(kExp, cudaFuncAttributeMaxDynamicSharedMemorySize, FUSED_SMEM);
    cudaFuncSetAttribute(kC2s, cudaFuncAttributeMaxDynamicSharedMemorySize, PIPE2_SMEM);
    cudaFuncSetAttribute(kDec, cudaFuncAttributeMaxDynamicSharedMemorySize, PIPE2_SMEM);

    // 0) pre-round X + weights to tf32 (rna), zero counts
    round_all<<<(RN_TOT / 4) / 256, 256>>>(X, enc_W, s2c_W, We1, We2, c2s_W, dec_W);

    // 1) fused encoder+s2c
    kEnc<<<dim3(S2C_SPLIT, NTOK / BM), 256, FUSED_SMEM>>>(
        Xr, encWr, enc_b, s2cWr, part_s2c, DDIM, DDIM, HDIM, nullptr, nullptr);

    // 2) routing
    router_kernel<<<NTOK, 64>>>(part_s2c, s2c_b, cont, rW1, rb1, rW2, rb2, ae, aw);

    // 3) fused expert MLP
    kExp<<<dim3(EXP_SPLIT, ECAP / BM, EEXP), 256, FUSED_SMEM>>>(
        cont, We1r, be1, We2r, part_exp, MDIM, MDIM, HHALF, bucket, count);

    // 4) combine
    combine_kernel<<<(NTOK * MDIM) / 256, 256>>>(part_exp, ae, aw, be2, outflat);

    // 5) c2s: sigmoid -> tf32-rounded spk_moe
    kC2s<<<dim3(HDIM / BN, NTOK / BM), 256, PIPE2_SMEM>>>(
        outflat, c2sWr, c2s_b, spk_moe, MDIM, HDIM);

    // 6) decoder: sigmoid -> fp32 decoded
    kDec<<<dim3(DDIM / BN, NTOK / BM), 256, PIPE2_SMEM>>>(
        spk_moe, decWr, dec_b, decoded, HDIM, DDIM);

    // 7) layernorm -> d_out
    layernorm_kernel<<<NTOK, 256>>>(decoded, ln_g, ln_b, (float*)d_out);
}

// round 6
// speedup vs baseline: 5.6167x; 1.0038x over previous
#include <cuda_runtime.h>
#include <math.h>

// Problem dims
#define NTOK 8192
#define DDIM 1024
#define HDIM 2048
#define MDIM 64
#define EEXP 8
#define HHALF 1024
#define ECAP 8192
#define NASSIGN (NTOK * 2)
#define S2C_SPLIT 16        // HDIM / 128
#define EXP_SPLIT 8         // HHALF / 128

// ---------------------------------------------------------------------------
// Scratch (device globals)
// ---------------------------------------------------------------------------
// tf32-rounded copies: [X | enc_W | s2c_W | We1 | We2 | c2s_W | dec_W]
#define RN_X   0UL
#define RN_EW  8388608UL
#define RN_SW  10485760UL
#define RN_W1  10616832UL
#define RN_W2  11141120UL
#define RN_CW  11665408UL
#define RN_DW  11796480UL
#define RN_TOT 13893632UL
__device__ float g_rnd[RN_TOT];

__device__ float g_part_s2c[(size_t)S2C_SPLIT * NTOK * MDIM];
__device__ float g_cont[(size_t)NTOK * MDIM];
__device__ int   g_assign_e[NASSIGN];
__device__ float g_assign_w[NASSIGN];
__device__ int   g_count[EEXP];
__device__ int   g_bucket[EEXP * ECAP];
__device__ float g_part_exp[(size_t)EXP_SPLIT * NASSIGN * MDIM];
__device__ float g_outflat[(size_t)NTOK * MDIM];
__device__ float g_spk_moe[(size_t)NTOK * HDIM];
__device__ float g_decoded[(size_t)NTOK * DDIM];

__device__ __forceinline__ unsigned f2tf(float x) {
    unsigned u;
    asm("cvt.rna.tf32.f32 %0, %1;" : "=r"(u) : "f"(x));
    return u;
}
__device__ __forceinline__ float rtf(float x) { return __uint_as_float(f2tf(x)); }
__device__ __forceinline__ void cp16(void* dst, const void* src) {
    unsigned d = (unsigned)__cvta_generic_to_shared(dst);
    asm volatile("cp.async.cg.shared.global [%0], [%1], 16;\n" :: "r"(d), "l"(src));
}
__device__ __forceinline__ void cp_commit() {
    asm volatile("cp.async.commit_group;\n");
}
template<int N> __device__ __forceinline__ void cp_wait() {
    asm volatile("cp.async.wait_group %0;\n" :: "n"(N));
}
__device__ __forceinline__ void mma_tf32(float c[4], const unsigned a[4], const unsigned b[2]) {
    asm volatile(
        "mma.sync.aligned.m16n8k8.row.col.f32.tf32.tf32.f32 "
        "{%0,%1,%2,%3}, {%4,%5,%6,%7}, {%8,%9}, {%0,%1,%2,%3};\n"
        : "+f"(c[0]), "+f"(c[1]), "+f"(c[2]), "+f"(c[3])
        : "r"(a[0]), "r"(a[1]), "r"(a[2]), "r"(a[3]), "r"(b[0]), "r"(b[1]));
}

// Geometry
#define BM 128
#define BN 128
#define AS 20
#define BS1 136
#define STAGES 4
#define PIPE_FLOATS (STAGES * (BM * AS + 16 * BS1))
#define SPIKE_S 132
#define W2_S 72
#define W2_OFF PIPE_FLOATS
#define FUSED_SMEM ((PIPE_FLOATS + 128 * W2_S) * 4)     // 112640 B

// Plain GEMM: BK=32, 3 stages
#define AS2 36
#define BS2 136
#define ST2 3
#define PIPE2_FLOATS (ST2 * (BM * AS2 + 32 * BS2))      // 26880
#define PIPE2_SMEM (PIPE2_FLOATS * 4)                   // 107520 B

// ---------------------------------------------------------------------------
// Pre-round X and all weights to tf32 (rna) into g_rnd; also zero counts.
// Destination is the contiguous g_rnd; sources selected by segment.
// ---------------------------------------------------------------------------
__global__ void round_all(const float* __restrict__ X,   const float* __restrict__ encW,
                          const float* __restrict__ s2cW, const float* __restrict__ We1,
                          const float* __restrict__ We2,  const float* __restrict__ c2sW,
                          const float* __restrict__ decW)
{
    if (blockIdx.x == 0 && threadIdx.x < EEXP) g_count[threadIdx.x] = 0;
    const size_t i = (size_t)blockIdx.x * 256 + threadIdx.x;   // float4 index
    const size_t f = i * 4;                                    // float index
    const float* src;
    size_t off;
    if      (f < RN_EW) { src = X;    off = f - RN_X;  }
    else if (f < RN_SW) { src = encW; off = f - RN_EW; }
    else if (f < RN_W1) { src = s2cW; off = f - RN_SW; }
    else if (f < RN_W2) { src = We1;  off = f - RN_W1; }
    else if (f < RN_CW) { src = We2;  off = f - RN_W2; }
    else if (f < RN_DW) { src = c2sW; off = f - RN_CW; }
    else                { src = decW; off = f - RN_DW; }
    float4 v = *(const float4*)&src[off];
    v.x = rtf(v.x); v.y = rtf(v.y); v.z = rtf(v.z); v.w = rtf(v.w);
    *(float4*)&g_rnd[f] = v;
}

// ---------------------------------------------------------------------------
// Fused GEMM+GEMM (inputs pre-rounded to tf32; raw-bit fragment reads).
//   EXPM=false: enc+s2c.   EXPM=true: expert MLP (gather/scatter).
// ---------------------------------------------------------------------------
template<bool EXPM>
__global__ __launch_bounds__(256, 2)
void fused_gemm2(const float* __restrict__ A, const float* __restrict__ W1,
                 const float* __restrict__ b1, const float* __restrict__ W2,
                 float* __restrict__ Cpart, int K, int lda, int ldw1,
                 const int* __restrict__ bucket, const int* __restrict__ count)
{
    extern __shared__ float sm[];
    float* spike = sm;
    float* w2s   = sm + W2_OFF;

    const int tid  = threadIdx.x;
    const int lane = tid & 31;
    const int w    = tid >> 5;
    const int g    = lane >> 2;
    const int tg   = lane & 3;
    const int wm   = w >> 2;
    const int wn   = w & 3;
    const int bm0  = blockIdx.y * BM;
    const int bn0  = blockIdx.x * BN;
    const int e    = EXPM ? blockIdx.z : 0;

    int cnt = 0;
    if (EXPM) {
        cnt = count[e];
        if (bm0 >= cnt) return;
    }

    const float* W1p = EXPM ? W1 + (size_t)e * MDIM * HHALF : W1;
    const float* b1p = EXPM ? b1 + (size_t)e * HHALF : b1;
    const float* W2p = EXPM ? W2 + (size_t)e * HHALF * MDIM : W2;

    constexpr int ALD = (BM * 16) / (256 * 4);
    constexpr int BLD = (16 * BN) / (256 * 4);
    size_t aoff[ALD];
#pragma unroll
    for (int it = 0; it < ALD; it++) {
        int idx  = tid + it * 256;
        int r    = idx >> 2;
        int grow = bm0 + r;
        if (EXPM) {
            int rr  = (grow < cnt) ? grow : (cnt - 1);
            int tok = bucket[e * ECAP + rr] >> 1;
            aoff[it] = (size_t)tok * MDIM;
        } else {
            aoff[it] = (size_t)grow * lda;
        }
    }

    // Prefetch W2 chunk as oldest cp.async group
#pragma unroll
    for (int it = 0; it < (128 * 64) / (256 * 4); it++) {
        int idx = tid + it * 256;
        int r   = idx >> 4;
        int c4  = idx & 15;
        cp16(&w2s[r * W2_S + c4 * 4], &W2p[(size_t)(bn0 + r) * MDIM + c4 * 4]);
    }
    cp_commit();

    float c[4][4][4];
#pragma unroll
    for (int i = 0; i < 4; i++)
#pragma unroll
        for (int j = 0; j < 4; j++)
#pragma unroll
            for (int q = 0; q < 4; q++) c[i][j][q] = 0.0f;

    const int nk = K / 16;
    auto issue = [&](int st, int kt) {
        const int k0 = kt * 16;
        float* as = sm + st * (BM * AS);
        float* bs = sm + STAGES * (BM * AS) + st * (16 * BS1);
#pragma unroll
        for (int it = 0; it < ALD; it++) {
            int idx = tid + it * 256;
            int r   = idx >> 2;
            int c4  = idx & 3;
            cp16(&as[r * AS + c4 * 4], A + aoff[it] + k0 + c4 * 4);
        }
#pragma unroll
        for (int it = 0; it < BLD; it++) {
            int idx = tid + it * 256;
            int r   = idx >> 5;
            int c4  = idx & 31;
            cp16(&bs[r * BS1 + c4 * 4],
                 &W1p[(size_t)(k0 + r) * ldw1 + bn0 + c4 * 4]);
        }
    };

#pragma unroll
    for (int s = 0; s < STAGES - 1; s++) {
        if (s < nk) issue(s, s);
        cp_commit();
    }

    for (int kt = 0; kt < nk; kt++) {
        cp_wait<STAGES - 2>();
        __syncthreads();
        const int st = kt % STAGES;
        const float* as = sm + st * (BM * AS);
        const float* bs = sm + STAGES * (BM * AS) + st * (16 * BS1);
#pragma unroll
        for (int ks = 0; ks < 2; ks++) {
            unsigned a[4][4], b[4][2];
#pragma unroll
            for (int mf = 0; mf < 4; mf++) {
                const int m0 = wm * 64 + mf * 16;
                a[mf][0] = __float_as_uint(as[(m0 + g)     * AS + ks * 8 + tg]);
                a[mf][1] = __float_as_uint(as[(m0 + g + 8) * AS + ks * 8 + tg]);
                a[mf][2] = __float_as_uint(as[(m0 + g)     * AS + ks * 8 + tg + 4]);
                a[mf][3] = __float_as_uint(as[(m0 + g + 8) * AS + ks * 8 + tg + 4]);
            }
#pragma unroll
            for (int nf = 0; nf < 4; nf++) {
                const int n0 = wn * 32 + nf * 8 + g;
                b[nf][0] = __float_as_uint(bs[(ks * 8 + tg)     * BS1 + n0]);
                b[nf][1] = __float_as_uint(bs[(ks * 8 + tg + 4) * BS1 + n0]);
            }
#pragma unroll
            for (int mf = 0; mf < 4; mf++)
#pragma unroll
                for (int nf = 0; nf < 4; nf++) mma_tf32(c[mf][nf], a[mf], b[nf]);
        }
        const int nxt = kt + STAGES - 1;
        if (nxt < nk) issue(nxt % STAGES, nxt);
        cp_commit();
    }

    cp_wait<0>();
    __syncthreads();
    // Activated tile -> smem, rounded to tf32 (bit-exact vs per-read cvt)
#pragma unroll
    for (int mf = 0; mf < 4; mf++) {
#pragma unroll
        for (int nf = 0; nf < 4; nf++) {
            const int col = wn * 32 + nf * 8 + 2 * tg;
            const int r0  = wm * 64 + mf * 16 + g;
#pragma unroll
            for (int half = 0; half < 2; half++) {
                const int row = r0 + half * 8;
                float v0 = c[mf][nf][half * 2 + 0] + b1p[bn0 + col];
                float v1 = c[mf][nf][half * 2 + 1] + b1p[bn0 + col + 1];
                if (EXPM) {
                    v0 = fmaxf(v0, 0.0f);
                    v1 = fmaxf(v1, 0.0f);
                } else {
                    v0 = 1.0f / (1.0f + expf(-v0));
                    v1 = 1.0f / (1.0f + expf(-v1));
                }
                *(float2*)&spike[row * SPIKE_S + col] = make_float2(rtf(v0), rtf(v1));
            }
        }
    }
    __syncthreads();

    // Second GEMM: part[128x64] = spike(128x128) @ w2s(128x64)
    const int wm2 = w >> 1;
    const int wn2 = w & 1;
    float c2[2][4][4];
#pragma unroll
    for (int i = 0; i < 2; i++)
#pragma unroll
        for (int j = 0; j < 4; j++)
#pragma unroll
            for (int q = 0; q < 4; q++) c2[i][j][q] = 0.0f;

#pragma unroll
    for (int ks = 0; ks < 16; ks++) {
        unsigned a[2][4], b[4][2];
#pragma unroll
        for (int mf = 0; mf < 2; mf++) {
            const int m0 = wm2 * 32 + mf * 16;
            a[mf][0] = __float_as_uint(spike[(m0 + g)     * SPIKE_S + ks * 8 + tg]);
            a[mf][1] = __float_as_uint(spike[(m0 + g + 8) * SPIKE_S + ks * 8 + tg]);
            a[mf][2] = __float_as_uint(spike[(m0 + g)     * SPIKE_S + ks * 8 + tg + 4]);
            a[mf][3] = __float_as_uint(spike[(m0 + g + 8) * SPIKE_S + ks * 8 + tg + 4]);
        }
#pragma unroll
        for (int nf = 0; nf < 4; nf++) {
            const int n0 = wn2 * 32 + nf * 8 + g;
            b[nf][0] = __float_as_uint(w2s[(ks * 8 + tg)     * W2_S + n0]);
            b[nf][1] = __float_as_uint(w2s[(ks * 8 + tg + 4) * W2_S + n0]);
        }
#pragma unroll
        for (int mf = 0; mf < 2; mf++)
#pragma unroll
            for (int nf = 0; nf < 4; nf++) mma_tf32(c2[mf][nf], a[mf], b[nf]);
    }

    const size_t split_base = (size_t)blockIdx.x * (EXPM ? NASSIGN : NTOK) * MDIM;
#pragma unroll
    for (int mf = 0; mf < 2; mf++) {
#pragma unroll
        for (int nf = 0; nf < 4; nf++) {
            const int col = wn2 * 32 + nf * 8 + 2 * tg;
            const int r0  = wm2 * 32 + mf * 16 + g;
#pragma unroll
            for (int half = 0; half < 2; half++) {
                const int row = r0 + half * 8;
                float v0 = c2[mf][nf][half * 2 + 0];
                float v1 = c2[mf][nf][half * 2 + 1];
                if (EXPM) {
                    if (bm0 + row < cnt) {
                        const int i = bucket[e * ECAP + bm0 + row];
                        *(float2*)&Cpart[split_base + (size_t)i * MDIM + col] =
                            make_float2(v0, v1);
                    }
                } else {
                    *(float2*)&Cpart[split_base + (size_t)(bm0 + row) * MDIM + col] =
                        make_float2(v0, v1);
                }
            }
        }
    }
}

// ---------------------------------------------------------------------------
// Plain multistage tf32 GEMM, BK=32, 3 stages. Sigmoid epilogue.
// ROUND=1: store tf32-rounded (feeds next GEMM). ROUND=0: store fp32.
// ---------------------------------------------------------------------------
template<int ROUND>
__global__ __launch_bounds__(256, 2)
void mma_gemm(const float* __restrict__ A, const float* __restrict__ W,
              const float* __restrict__ bias, float* __restrict__ C,
              int K, int Hout)
{
    extern __shared__ float sm[];
    const int tid  = threadIdx.x;
    const int lane = tid & 31;
    const int w    = tid >> 5;
    const int g    = lane >> 2;
    const int tg   = lane & 3;
    const int wm   = w >> 2;
    const int wn   = w & 3;
    const int bm0  = blockIdx.y * BM;
    const int bn0  = blockIdx.x * BN;

    constexpr int ALD = (BM * 32) / (256 * 4);   // 4
    constexpr int BLD = (32 * BN) / (256 * 4);   // 4

    float c[4][4][4];
#pragma unroll
    for (int i = 0; i < 4; i++)
#pragma unroll
        for (int j = 0; j < 4; j++)
#pragma unroll
            for (int q = 0; q < 4; q++) c[i][j][q] = 0.0f;

    const int nk = K / 32;
    auto issue = [&](int st, int kt) {
        const int k0 = kt * 32;
        float* as = sm + st * (BM * AS2);
        float* bs = sm + ST2 * (BM * AS2) + st * (32 * BS2);
#pragma unroll
        for (int it = 0; it < ALD; it++) {
            int idx = tid + it * 256;
            int r   = idx >> 3;           // 8 float4 per 32-wide row
            int c4  = idx & 7;
            cp16(&as[r * AS2 + c4 * 4], &A[(size_t)(bm0 + r) * K + k0 + c4 * 4]);
        }
#pragma unroll
        for (int it = 0; it < BLD; it++) {
            int idx = tid + it * 256;
            int r   = idx >> 5;           // 32 float4 per row
            int c4  = idx & 31;
            cp16(&bs[r * BS2 + c4 * 4], &W[(size_t)(k0 + r) * Hout + bn0 + c4 * 4]);
        }
    };

#pragma unroll
    for (int s = 0; s < ST2 - 1; s++) {
        if (s < nk) issue(s, s);
        cp_commit();
    }

    for (int kt = 0; kt < nk; kt++) {
        cp_wait<ST2 - 2>();
        __syncthreads();
        const int st = kt % ST2;
        const float* as = sm + st * (BM * AS2);
        const float* bs = sm + ST2 * (BM * AS2) + st * (32 * BS2);
#pragma unroll
        for (int ks = 0; ks < 4; ks++) {
            unsigned a[4][4], b[4][2];
#pragma unroll
            for (int mf = 0; mf < 4; mf++) {
                const int m0 = wm * 64 + mf * 16;
                a[mf][0] = __float_as_uint(as[(m0 + g)     * AS2 + ks * 8 + tg]);
                a[mf][1] = __float_as_uint(as[(m0 + g + 8) * AS2 + ks * 8 + tg]);
                a[mf][2] = __float_as_uint(as[(m0 + g)     * AS2 + ks * 8 + tg + 4]);
                a[mf][3] = __float_as_uint(as[(m0 + g + 8) * AS2 + ks * 8 + tg + 4]);
            }
#pragma unroll
            for (int nf = 0; nf < 4; nf++) {
                const int n0 = wn * 32 + nf * 8 + g;
                b[nf][0] = __float_as_uint(bs[(ks * 8 + tg)     * BS2 + n0]);
                b[nf][1] = __float_as_uint(bs[(ks * 8 + tg + 4) * BS2 + n0]);
            }
#pragma unroll
            for (int mf = 0; mf < 4; mf++)
#pragma unroll
                for (int nf = 0; nf < 4; nf++) mma_tf32(c[mf][nf], a[mf], b[nf]);
        }
        const int nxt = kt + ST2 - 1;
        if (nxt < nk) issue(nxt % ST2, nxt);
        cp_commit();
    }

#pragma unroll
    for (int mf = 0; mf < 4; mf++) {
#pragma unroll
        for (int nf = 0; nf < 4; nf++) {
            const int col = bn0 + wn * 32 + nf * 8 + 2 * tg;
            const int r0  = bm0 + wm * 64 + mf * 16 + g;
#pragma unroll
            for (int half = 0; half < 2; half++) {
                const int row = r0 + half * 8;
                float v0 = c[mf][nf][half * 2 + 0] + bias[col];
                float v1 = c[mf][nf][half * 2 + 1] + bias[col + 1];
                v0 = 1.0f / (1.0f + expf(-v0));
                v1 = 1.0f / (1.0f + expf(-v1));
                if (ROUND) { v0 = rtf(v0); v1 = rtf(v1); }
                *(float2*)&C[(size_t)row * Hout + col] = make_float2(v0, v1);
            }
        }
    }
}

// ---------------------------------------------------------------------------
// Router: reduce 16 s2c partials + bias -> cont (stored tf32-rounded);
// router MLP (fp32); top-2; bucket.
// ---------------------------------------------------------------------------
__global__ void router_kernel(const float* __restrict__ part_s2c,
                              const float* __restrict__ s2c_b,
                              float* __restrict__ cont,
                              const float* __restrict__ rW1, const float* __restrict__ rb1,
                              const float* __restrict__ rW2, const float* __restrict__ rb2,
                              int* __restrict__ assign_e, float* __restrict__ assign_w)
{
    __shared__ float cs[64];
    __shared__ float hid[64];
    __shared__ float logit[8];
    const int n = blockIdx.x;
    const int t = threadIdx.x;

    float cv = s2c_b[t];
#pragma unroll
    for (int s = 0; s < S2C_SPLIT; s++)
        cv += part_s2c[(size_t)s * NTOK * MDIM + (size_t)n * MDIM + t];
    cont[(size_t)n * MDIM + t] = rtf(cv);   // expert GEMM consumes tf32 bits
    cs[t] = cv;                              // router MLP uses full fp32
    __syncthreads();

    float a = rb1[t];
#pragma unroll
    for (int m = 0; m < 64; m++) a = fmaf(cs[m], rW1[m * 64 + t], a);
    hid[t] = tanhf(a);
    __syncthreads();

    if (t < EEXP) {
        float l = rb2[t];
#pragma unroll
        for (int j = 0; j < 64; j++) l = fmaf(hid[j], rW2[j * EEXP + t], l);
        logit[t] = l;
    }
    __syncthreads();

    if (t == 0) {
        float mx = logit[0];
        for (int e = 1; e < EEXP; e++) mx = fmaxf(mx, logit[e]);
        float p[EEXP];
        for (int e = 0; e < EEXP; e++) p[e] = expf(logit[e] - mx);
        int i1 = 0;
        for (int e = 1; e < EEXP; e++) if (p[e] > p[i1]) i1 = e;
        int i2 = (i1 == 0) ? 1 : 0;
        for (int e = 0; e < EEXP; e++) if (e != i1 && p[e] > p[i2]) i2 = e;
        const float denom = p[i1] + p[i2];
        const int   ids[2] = {i1, i2};
        const float ws[2]  = {p[i1] / denom, p[i2] / denom};
#pragma unroll
        for (int k = 0; k < 2; k++) {
            const int i = n * 2 + k;
            assign_e[i] = ids[k];
            assign_w[i] = ws[k];
            const int slot = atomicAdd(&g_count[ids[k]], 1);
            g_bucket[ids[k] * ECAP + slot] = i;
        }
    }
}

// Combine: outflat (tf32-rounded; consumed by c2s GEMM)
__global__ void combine_kernel(const float* __restrict__ part_exp,
                               const int* __restrict__ ae, const float* __restrict__ aw,
                               const float* __restrict__ be2,
                               float* __restrict__ outflat)
{
    const int i = blockIdx.x * 256 + threadIdx.x;
    const int n = i >> 6;
    const int m = i & 63;
    float acc = 0.0f;
#pragma unroll
    for (int k = 0; k < 2; k++) {
        const int idx = 2 * n + k;
        float s = be2[ae[idx] * MDIM + m];
#pragma unroll
        for (int sp = 0; sp < EXP_SPLIT; sp++)
            s += part_exp[(size_t)sp * NASSIGN * MDIM + (size_t)idx * MDIM + m];
        acc = fmaf(aw[idx], s, acc);
    }
    outflat[i] = rtf(acc);
}

// LayerNorm over D=1024
__global__ void layernorm_kernel(const float* __restrict__ x,
                                 const float* __restrict__ g, const float* __restrict__ b,
                                 float* __restrict__ out)
{
    const int n = blockIdx.x;
    const int t = threadIdx.x;
    const float* row = x + (size_t)n * DDIM;

    float v[4];
    float s = 0.0f, s2 = 0.0f;
#pragma unroll
    for (int i = 0; i < 4; i++) {
        v[i] = row[t + i * 256];
        s += v[i];
        s2 += v[i] * v[i];
    }
#pragma unroll
    for (int o = 16; o > 0; o >>= 1) {
        s  += __shfl_xor_sync(0xFFFFFFFFu, s, o);
        s2 += __shfl_xor_sync(0xFFFFFFFFu, s2, o);
    }
    __shared__ float sh1[8], sh2[8];
    __shared__ float mu_s, rstd_s;
    const int warp = t >> 5, lane = t & 31;
    if (lane == 0) { sh1[warp] = s; sh2[warp] = s2; }
    __syncthreads();
    if (t == 0) {
        float S = 0.0f, S2 = 0.0f;
        for (int wq = 0; wq < 8; wq++) { S += sh1[wq]; S2 += sh2[wq]; }
        float mu  = S / (float)DDIM;
        float var = S2 / (float)DDIM - mu * mu;
        mu_s   = mu;
        rstd_s = rsqrtf(var + 1e-5f);
    }
    __syncthreads();
    const float mu = mu_s, rstd = rstd_s;
    float* orow = out + (size_t)n * DDIM;
#pragma unroll
    for (int i = 0; i < 4; i++) {
        int col = t + i * 256;
        orow[col] = (v[i] - mu) * rstd * g[col] + b[col];
    }
}

// ---------------------------------------------------------------------------
extern "C" void kernel_launch(void* const* d_in, const int* in_sizes, int n_in,
                              void* d_out, int out_size)
{
    const float* X     = (const float*)d_in[0];
    const float* enc_W = (const float*)d_in[1];
    const float* enc_b = (const float*)d_in[2];
    const float* s2c_W = (const float*)d_in[3];
    const float* s2c_b = (const float*)d_in[4];
    const float* rW1   = (const float*)d_in[5];
    const float* rb1   = (const float*)d_in[6];
    const float* rW2   = (const float*)d_in[7];
    const float* rb2   = (const float*)d_in[8];
    const float* We1   = (const float*)d_in[9];
    const float* be1   = (const float*)d_in[10];
    const float* We2   = (const float*)d_in[11];
    const float* be2   = (const float*)d_in[12];
    const float* c2s_W = (const float*)d_in[13];
    const float* c2s_b = (const float*)d_in[14];
    const float* dec_W = (const float*)d_in[15];
    const float* dec_b = (const float*)d_in[16];
    const float* ln_g  = (const float*)d_in[17];
    const float* ln_b  = (const float*)d_in[18];

    float *rnd, *part_s2c, *cont, *aw, *part_exp, *outflat, *spk_moe, *decoded;
    int *ae, *bucket, *count;
    cudaGetSymbolAddress((void**)&rnd,      g_rnd);
    cudaGetSymbolAddress((void**)&part_s2c, g_part_s2c);
    cudaGetSymbolAddress((void**)&cont,     g_cont);
    cudaGetSymbolAddress((void**)&ae,       g_assign_e);
    cudaGetSymbolAddress((void**)&aw,       g_assign_w);
    cudaGetSymbolAddress((void**)&count,    g_count);
    cudaGetSymbolAddress((void**)&bucket,   g_bucket);
    cudaGetSymbolAddress((void**)&part_exp, g_part_exp);
    cudaGetSymbolAddress((void**)&outflat,  g_outflat);
    cudaGetSymbolAddress((void**)&spk_moe,  g_spk_moe);
    cudaGetSymbolAddress((void**)&decoded,  g_decoded);

    const float* Xr    = rnd + RN_X;
    const float* encWr = rnd + RN_EW;
    const float* s2cWr = rnd + RN_SW;
    const float* We1r  = rnd + RN_W1;
    const float* We2r  = rnd + RN_W2;
    const float* c2sWr = rnd + RN_CW;
    const float* decWr = rnd + RN_DW;

    auto kEnc = fused_gemm2<false>;
    auto kExp = fused_gemm2<true>;
    auto kC2s = mma_gemm<1>;
    auto kDec = mma_gemm<0>;

    cudaFuncSetAttribute(kEnc, cudaFuncAttributeMaxDynamicSharedMemorySize, FUSED_SMEM);
    cudaFuncSetAttribute(kExp, cudaFuncAttributeMaxDynamicSharedMemorySize, FUSED_SMEM);
    cudaFuncSetAttribute(kC2s, cudaFuncAttributeMaxDynamicSharedMemorySize, PIPE2_SMEM);
    cudaFuncSetAttribute(kDec, cudaFuncAttributeMaxDynamicSharedMemorySize, PIPE2_SMEM);

    // 0) pre-round X + weights to tf32 (rna), zero counts
    round_all<<<(RN_TOT / 4) / 256, 256>>>(X, enc_W, s2c_W, We1, We2, c2s_W, dec_W);

    // 1) fused encoder+s2c
    kEnc<<<dim3(S2C_SPLIT, NTOK / BM), 256, FUSED_SMEM>>>(
        Xr, encWr, enc_b, s2cWr, part_s2c, DDIM, DDIM, HDIM, nullptr, nullptr);

    // 2) routing
    router_kernel<<<NTOK, 64>>>(part_s2c, s2c_b, cont, rW1, rb1, rW2, rb2, ae, aw);

    // 3) fused expert MLP
    kExp<<<dim3(EXP_SPLIT, ECAP / BM, EEXP), 256, FUSED_SMEM>>>(
        cont, We1r, be1, We2r, part_exp, MDIM, MDIM, HHALF, bucket, count);

    // 4) combine
    combine_kernel<<<(NTOK * MDIM) / 256, 256>>>(part_exp, ae, aw, be2, outflat);

    // 5) c2s: sigmoid -> tf32-rounded spk_moe
    kC2s<<<dim3(HDIM / BN, NTOK / BM), 256, PIPE2_SMEM>>>(
        outflat, c2sWr, c2s_b, spk_moe, MDIM, HDIM);

    // 6) decoder: sigmoid -> fp32 decoded
    kDec<<<dim3(DDIM / BN, NTOK / BM), 256, PIPE2_SMEM>>>(
        spk_moe, decWr, dec_b, decoded, HDIM, DDIM);

    // 7) layernorm -> d_out
    layernorm_kernel<<<NTOK, 256>>>(decoded, ln_g, ln_b, (float*)d_out);
}